// round 1
// baseline (speedup 1.0000x reference)
#include <cuda_runtime.h>

#define EPS 1e-5f

// Scratch for intermediate feature maps (no cudaMalloc allowed).
__device__ float g_zf[64 * 256 * 14 * 14];   // ~12.8 MB
__device__ float g_xf[64 * 256 * 30 * 30];   // ~59 MB

// ---------------------------------------------------------------------------
// Implicit-GEMM 3x3 VALID conv + fused inference BatchNorm.
//   A = weights   [Ch=256, K=Cin*9=2304]  (OIHW flattening == row-major A)
//   B = im2col(x) [K, N=B*OH*OW]          (gathered on the fly)
//   C[c, n] -> out[b, c, oh, ow] * scale[c] + bias[c]
// Tiles: BM=128, BN=128, BK=16, 256 threads, 8x8 per thread.
// All dims divide the tiles exactly (57600/128, 12544/128, 2304/16) -> no tails.
// ---------------------------------------------------------------------------
template <int OH, int OW, int IH, int IW>
__global__ __launch_bounds__(256, 2)
void conv3x3_bn_kernel(const float* __restrict__ inp,    // [B, 256, IH, IW]
                       const float* __restrict__ w,      // [256, 2304]
                       const float* __restrict__ gamma,
                       const float* __restrict__ beta,
                       const float* __restrict__ mean,
                       const float* __restrict__ var,
                       float* __restrict__ out)          // [B, 256, OH, OW]
{
    constexpr int C  = 256;
    constexpr int K  = C * 9;
    constexpr int BM = 128, BN = 128, BK = 16;

    const int n0  = blockIdx.x * BN;
    const int m0  = blockIdx.y * BM;
    const int tid = threadIdx.x;
    const int tx  = tid & 15;   // n-direction (8 cols each)
    const int ty  = tid >> 4;   // m-direction (8 rows each)

    __shared__ float As[BK][BM];
    __shared__ float Bs[BK][BN];

    float acc[8][8];
#pragma unroll
    for (int i = 0; i < 8; i++)
#pragma unroll
        for (int j = 0; j < 8; j++) acc[i][j] = 0.f;

    // B-tile gather mapping: one n per thread (fixed), 8 k's per thread.
    const int n_off  = tid & 127;
    const int k_half = tid >> 7;           // 0 or 1
    const int n      = n0 + n_off;
    const int b      = n / (OH * OW);
    const int rem    = n - b * (OH * OW);
    const int oh     = rem / OW;
    const int ow     = rem - oh * OW;
    const float* inp_b = inp + (size_t)b * C * IH * IW;

    for (int k0 = 0; k0 < K; k0 += BK) {
        // ---- load A tile (weights), float4 along k, store transposed ----
#pragma unroll
        for (int i = 0; i < 2; i++) {
            int idx = tid + i * 256;           // 0..511 float4 slots
            int row = idx >> 2;                // 0..127  (m within tile)
            int c4  = idx & 3;                 // which float4 in the 16-k row
            float4 v = *reinterpret_cast<const float4*>(
                &w[(size_t)(m0 + row) * K + k0 + c4 * 4]);
            As[c4 * 4 + 0][row] = v.x;
            As[c4 * 4 + 1][row] = v.y;
            As[c4 * 4 + 2][row] = v.z;
            As[c4 * 4 + 3][row] = v.w;
        }
        // ---- load B tile (im2col gather) ----
#pragma unroll
        for (int kk2 = 0; kk2 < 8; kk2++) {
            int k_local = k_half * 8 + kk2;
            int k  = k0 + k_local;
            int ci = k / 9;
            int r9 = k - ci * 9;
            int kh = r9 / 3;
            int kw = r9 - kh * 3;
            Bs[k_local][n_off] =
                __ldg(&inp_b[(ci * IH + oh + kh) * IW + ow + kw]);
        }
        __syncthreads();

#pragma unroll
        for (int kk = 0; kk < BK; kk++) {
            float ra[8], rb[8];
#pragma unroll
            for (int i = 0; i < 8; i++) ra[i] = As[kk][ty * 8 + i];
#pragma unroll
            for (int j = 0; j < 8; j++) rb[j] = Bs[kk][tx * 8 + j];
#pragma unroll
            for (int i = 0; i < 8; i++)
#pragma unroll
                for (int j = 0; j < 8; j++)
                    acc[i][j] = fmaf(ra[i], rb[j], acc[i][j]);
        }
        __syncthreads();
    }

    // ---- epilogue: fused BN + scatter to NCHW ----
    float s[8], bi[8];
#pragma unroll
    for (int i = 0; i < 8; i++) {
        int c    = m0 + ty * 8 + i;
        float g  = __ldg(&gamma[c]);
        float mn = __ldg(&mean[c]);
        float vr = __ldg(&var[c]);
        float be = __ldg(&beta[c]);
        float sc = g * rsqrtf(vr + EPS);
        s[i]  = sc;
        bi[i] = be - mn * sc;
    }
#pragma unroll
    for (int j = 0; j < 8; j++) {
        int nn  = n0 + tx * 8 + j;
        int bb  = nn / (OH * OW);
        int rr  = nn - bb * (OH * OW);
        int ohh = rr / OW;
        int oww = rr - ohh * OW;
#pragma unroll
        for (int i = 0; i < 8; i++) {
            int c = m0 + ty * 8 + i;
            out[(((size_t)bb * C + c) * OH + ohh) * OW + oww] =
                acc[i][j] * s[i] + bi[i];
        }
    }
}

// ---------------------------------------------------------------------------
// Depthwise cross-correlation: out[b,c,oh,ow] = sum_{p,q} zf[b,c,p,q] *
// xf[b,c,oh+p,ow+q].  One thread per (b*c, oh) output row: 17 accumulators,
// xf row cached in 30 registers, zf broadcast from L1.
// 5.4 FMA per load -> FMA-issue bound, ~3.3K FMA/thread.
// ---------------------------------------------------------------------------
__global__ __launch_bounds__(256)
void xcorr_kernel(const float* __restrict__ zf,   // [BC, 14, 14]
                  const float* __restrict__ xf,   // [BC, 30, 30]
                  float* __restrict__ out)        // [BC, 17, 17]
{
    int g = blockIdx.x * blockDim.x + threadIdx.x;
    if (g >= 64 * 256 * 17) return;
    int oh = g % 17;
    int bc = g / 17;

    const float* zp = zf + bc * 196;
    const float* xp = xf + bc * 900;

    float acc[17];
#pragma unroll
    for (int j = 0; j < 17; j++) acc[j] = 0.f;

#pragma unroll 1
    for (int p = 0; p < 14; p++) {
        const float* row = xp + (oh + p) * 30;
        float xr[30];
#pragma unroll
        for (int t = 0; t < 30; t++) xr[t] = __ldg(row + t);
#pragma unroll
        for (int q = 0; q < 14; q++) {
            float zv = __ldg(zp + p * 14 + q);
#pragma unroll
            for (int j = 0; j < 17; j++)
                acc[j] = fmaf(zv, xr[q + j], acc[j]);
        }
    }

    float* op = out + bc * 289 + oh * 17;
#pragma unroll
    for (int j = 0; j < 17; j++) op[j] = acc[j];
}

// ---------------------------------------------------------------------------
extern "C" void kernel_launch(void* const* d_in, const int* in_sizes, int n_in,
                              void* d_out, int out_size)
{
    const float* z       = (const float*)d_in[0];
    const float* x       = (const float*)d_in[1];
    const float* w_z     = (const float*)d_in[2];
    const float* w_x     = (const float*)d_in[3];
    const float* gamma_z = (const float*)d_in[4];
    const float* beta_z  = (const float*)d_in[5];
    const float* mean_z  = (const float*)d_in[6];
    const float* var_z   = (const float*)d_in[7];
    const float* gamma_x = (const float*)d_in[8];
    const float* beta_x  = (const float*)d_in[9];
    const float* mean_x  = (const float*)d_in[10];
    const float* var_x   = (const float*)d_in[11];
    float* out = (float*)d_out;

    float *zf, *xf;
    cudaGetSymbolAddress((void**)&zf, g_zf);
    cudaGetSymbolAddress((void**)&xf, g_xf);

    // z branch: [64,256,16,16] -> [64,256,14,14]; N = 12544 = 98 * 128
    dim3 gz(98, 2);
    conv3x3_bn_kernel<14, 14, 16, 16><<<gz, 256>>>(
        z, w_z, gamma_z, beta_z, mean_z, var_z, zf);

    // x branch: [64,256,32,32] -> [64,256,30,30]; N = 57600 = 450 * 128
    dim3 gx(450, 2);
    conv3x3_bn_kernel<30, 30, 32, 32><<<gx, 256>>>(
        x, w_x, gamma_x, beta_x, mean_x, var_x, xf);

    // xcorr: 64*256*17 = 278528 threads = 1088 * 256
    xcorr_kernel<<<1088, 256>>>(zf, xf, out);
}

// round 3
// speedup vs baseline: 1.3937x; 1.3937x over previous
#include <cuda_runtime.h>
#include <cuda_bf16.h>
#include <mma.h>
#include <cstdint>

using namespace nvcuda;

#define EPS 1e-5f

// Scratch feature maps (no cudaMalloc allowed).
__device__ __align__(16) float g_zf[64 * 256 * 14 * 14];   // ~12.8 MB
__device__ __align__(16) float g_xf[64 * 256 * 30 * 30];   // ~59 MB

// ===========================================================================
// Implicit-GEMM 3x3 VALID conv + fused BN via bf16 wmma (HMMA) with hi/lo
// 3-split fp32 emulation:  a*b ~= ah*bh + ah*bl + al*bh   (err ~2^-18).
//   C[m,n] = sum_k W[m,k] * im2col[k,n]
//   M=256 (out ch), K=2304, N=B*OH*OW.
// Tiles: BM=128, BN=128, BK=32. 8 warps, warp tile 64(m) x 32(n).
// Double-buffered SMEM, padded stride 40 (conflict-free ldmatrix).
// ===========================================================================
template <int OH, int OW, int IH, int IW>
__global__ __launch_bounds__(256, 1)
void conv3x3_bn_wmma(const float* __restrict__ inp,    // [B,256,IH,IW]
                     const float* __restrict__ w,      // [256,2304]
                     const float* __restrict__ gamma,
                     const float* __restrict__ beta,
                     const float* __restrict__ mean,
                     const float* __restrict__ var,
                     float* __restrict__ out)          // [B,256,OH,OW]
{
    constexpr int C = 256, K = C * 9;
    constexpr int BM = 128, BN = 128, BK = 32;
    constexpr int NCH = K / BK;           // 72
    constexpr int OHW = OH * OW;
    constexpr int LDA = 40;               // bf16 elems per row (padded)
    constexpr int LDC = 132;              // fp32 elems per row (padded)
    constexpr uint32_t TILE_B = BM * LDA * 2;   // 10240 bytes per operand tile

    extern __shared__ char smem[];
    // layout: [A_hi b0,b1][A_lo b0,b1][B_hi b0,b1][B_lo b0,b1] = 8 * 10240
    char* const base = smem;

    const int tid = threadIdx.x;
    const int wid = tid >> 5;
    const int m0 = blockIdx.y * BM;
    const int n0 = blockIdx.x * BN;
    const int wm = (wid & 1) * 64;        // warp m-offset
    const int wn = (wid >> 1) * 32;       // warp n-offset

    // ---- per-thread fill mappings ----
    // A: 2 threads per weight row, 16 k each.
    const int arow  = tid >> 1;
    const int akoff = (tid & 1) * 16;
    const float* wr = w + (size_t)(m0 + arow) * K + akoff;
    // B: thread handles n = tid&127, k-half = (tid>>7)*16.
    const int n_loc  = tid & 127;
    const int bkoff  = (tid >> 7) * 16;
    const int n      = n0 + n_loc;
    const int b_     = n / OHW;
    const int rem    = n - b_ * OHW;
    const int ohh    = rem / OW;
    const int oww    = rem - ohh * OW;
    const float* xb  = inp + (size_t)b_ * C * IH * IW + (size_t)ohh * IW + oww;

    auto fill = [&](int ch) {
        const int buf = ch & 1;
        const int k0 = ch * BK;
        uint32_t* sa_hi = (uint32_t*)(base + 0 * TILE_B + buf * TILE_B);
        uint32_t* sa_lo = (uint32_t*)(base + 2 * TILE_B + buf * TILE_B);
        uint32_t* sb_hi = (uint32_t*)(base + 4 * TILE_B + buf * TILE_B);
        uint32_t* sb_lo = (uint32_t*)(base + 6 * TILE_B + buf * TILE_B);
        // ---- A (weights): 4 float4 = 16 contiguous k ----
        {
            const float* wp = wr + k0;
            const int du = (arow * LDA + akoff) >> 1;   // uint32 index
#pragma unroll
            for (int i = 0; i < 4; i++) {
                float4 v = __ldg(reinterpret_cast<const float4*>(wp + i * 4));
                __nv_bfloat16 h0 = __float2bfloat16(v.x);
                __nv_bfloat16 h1 = __float2bfloat16(v.y);
                __nv_bfloat16 h2 = __float2bfloat16(v.z);
                __nv_bfloat16 h3 = __float2bfloat16(v.w);
                __nv_bfloat16 l0 = __float2bfloat16(v.x - __bfloat162float(h0));
                __nv_bfloat16 l1 = __float2bfloat16(v.y - __bfloat162float(h1));
                __nv_bfloat16 l2 = __float2bfloat16(v.z - __bfloat162float(h2));
                __nv_bfloat16 l3 = __float2bfloat16(v.w - __bfloat162float(h3));
                sa_hi[du + i * 2 + 0] = (uint32_t)__bfloat16_as_ushort(h0) |
                                        ((uint32_t)__bfloat16_as_ushort(h1) << 16);
                sa_hi[du + i * 2 + 1] = (uint32_t)__bfloat16_as_ushort(h2) |
                                        ((uint32_t)__bfloat16_as_ushort(h3) << 16);
                sa_lo[du + i * 2 + 0] = (uint32_t)__bfloat16_as_ushort(l0) |
                                        ((uint32_t)__bfloat16_as_ushort(l1) << 16);
                sa_lo[du + i * 2 + 1] = (uint32_t)__bfloat16_as_ushort(l2) |
                                        ((uint32_t)__bfloat16_as_ushort(l3) << 16);
            }
        }
        // ---- B (im2col gather): 16 k for this thread's n ----
        {
            int kg = k0 + bkoff;
            int ci = kg / 9;
            int r9 = kg - ci * 9;
            int kh = r9 / 3;
            int kw = r9 - kh * 3;
            const int du = (n_loc * LDA + bkoff) >> 1;
#pragma unroll
            for (int j = 0; j < 8; j++) {
                float a0 = __ldg(xb + (ci * IH + kh) * IW + kw);
                kw++; if (kw == 3) { kw = 0; kh++; if (kh == 3) { kh = 0; ci++; } }
                float a1 = __ldg(xb + (ci * IH + kh) * IW + kw);
                kw++; if (kw == 3) { kw = 0; kh++; if (kh == 3) { kh = 0; ci++; } }
                __nv_bfloat16 h0 = __float2bfloat16(a0);
                __nv_bfloat16 h1 = __float2bfloat16(a1);
                __nv_bfloat16 l0 = __float2bfloat16(a0 - __bfloat162float(h0));
                __nv_bfloat16 l1 = __float2bfloat16(a1 - __bfloat162float(h1));
                sb_hi[du + j] = (uint32_t)__bfloat16_as_ushort(h0) |
                                ((uint32_t)__bfloat16_as_ushort(h1) << 16);
                sb_lo[du + j] = (uint32_t)__bfloat16_as_ushort(l0) |
                                ((uint32_t)__bfloat16_as_ushort(l1) << 16);
            }
        }
    };

    wmma::fragment<wmma::accumulator, 16, 16, 16, float> acc[4][2];
#pragma unroll
    for (int i = 0; i < 4; i++)
#pragma unroll
        for (int j = 0; j < 2; j++) wmma::fill_fragment(acc[i][j], 0.0f);

    fill(0);

#pragma unroll 1
    for (int ch = 0; ch < NCH; ch++) {
        __syncthreads();
        if (ch + 1 < NCH) fill(ch + 1);

        const int buf = ch & 1;
        const __nv_bfloat16* sa_hi = (const __nv_bfloat16*)(base + 0 * TILE_B + buf * TILE_B);
        const __nv_bfloat16* sa_lo = (const __nv_bfloat16*)(base + 2 * TILE_B + buf * TILE_B);
        const __nv_bfloat16* sb_hi = (const __nv_bfloat16*)(base + 4 * TILE_B + buf * TILE_B);
        const __nv_bfloat16* sb_lo = (const __nv_bfloat16*)(base + 6 * TILE_B + buf * TILE_B);

#pragma unroll
        for (int ks = 0; ks < 2; ks++) {
            const int ko = ks * 16;
            wmma::fragment<wmma::matrix_a, 16, 16, 16, __nv_bfloat16, wmma::row_major> ah[4], al[4];
            wmma::fragment<wmma::matrix_b, 16, 16, 16, __nv_bfloat16, wmma::col_major> bh[2], bl[2];
#pragma unroll
            for (int i = 0; i < 4; i++) {
                wmma::load_matrix_sync(ah[i], sa_hi + (wm + i * 16) * LDA + ko, LDA);
                wmma::load_matrix_sync(al[i], sa_lo + (wm + i * 16) * LDA + ko, LDA);
            }
#pragma unroll
            for (int j = 0; j < 2; j++) {
                wmma::load_matrix_sync(bh[j], sb_hi + (wn + j * 16) * LDA + ko, LDA);
                wmma::load_matrix_sync(bl[j], sb_lo + (wn + j * 16) * LDA + ko, LDA);
            }
#pragma unroll
            for (int i = 0; i < 4; i++)
#pragma unroll
                for (int j = 0; j < 2; j++) {
                    wmma::mma_sync(acc[i][j], ah[i], bh[j], acc[i][j]);
                    wmma::mma_sync(acc[i][j], ah[i], bl[j], acc[i][j]);
                    wmma::mma_sync(acc[i][j], al[i], bh[j], acc[i][j]);
                }
        }
    }

    // ---- epilogue: acc -> SMEM C tile -> BN -> NCHW scatter ----
    __syncthreads();
    float* ct = (float*)base;              // 128 x LDC fp32 = 67.6 KB (fits)
#pragma unroll
    for (int i = 0; i < 4; i++)
#pragma unroll
        for (int j = 0; j < 2; j++)
            wmma::store_matrix_sync(ct + (wm + i * 16) * LDC + wn + j * 16,
                                    acc[i][j], LDC, wmma::mem_row_major);
    __syncthreads();

#pragma unroll 1
    for (int it = 0; it < 64; it++) {
        const int idx = tid + it * 256;
        const int m = idx >> 7;
        const int nl = idx & 127;
        const int c = m0 + m;
        const float sc = __ldg(&gamma[c]) * rsqrtf(__ldg(&var[c]) + EPS);
        const float bi = __ldg(&beta[c]) - __ldg(&mean[c]) * sc;
        const int nn = n0 + nl;
        const int b2 = nn / OHW;
        const int s  = nn - b2 * OHW;
        out[((size_t)b2 * C + c) * OHW + s] = ct[m * LDC + nl] * sc + bi;
    }
}

// ===========================================================================
// Depthwise cross-correlation (unchanged; passes, ~FMA-bound).
// ===========================================================================
__global__ __launch_bounds__(256)
void xcorr_kernel(const float* __restrict__ zf,   // [BC,14,14]
                  const float* __restrict__ xf,   // [BC,30,30]
                  float* __restrict__ out)        // [BC,17,17]
{
    int g = blockIdx.x * blockDim.x + threadIdx.x;
    if (g >= 64 * 256 * 17) return;
    int oh = g % 17;
    int bc = g / 17;

    const float* zp = zf + bc * 196;
    const float* xp = xf + bc * 900;

    float acc[17];
#pragma unroll
    for (int j = 0; j < 17; j++) acc[j] = 0.f;

#pragma unroll 1
    for (int p = 0; p < 14; p++) {
        const float* row = xp + (oh + p) * 30;
        float xr[30];
#pragma unroll
        for (int t = 0; t < 30; t++) xr[t] = __ldg(row + t);
#pragma unroll
        for (int q = 0; q < 14; q++) {
            float zv = __ldg(zp + p * 14 + q);
#pragma unroll
            for (int j = 0; j < 17; j++)
                acc[j] = fmaf(zv, xr[q + j], acc[j]);
        }
    }

    float* op = out + bc * 289 + oh * 17;
#pragma unroll
    for (int j = 0; j < 17; j++) op[j] = acc[j];
}

// ===========================================================================
extern "C" void kernel_launch(void* const* d_in, const int* in_sizes, int n_in,
                              void* d_out, int out_size)
{
    const float* z       = (const float*)d_in[0];
    const float* x       = (const float*)d_in[1];
    const float* w_z     = (const float*)d_in[2];
    const float* w_x     = (const float*)d_in[3];
    const float* gamma_z = (const float*)d_in[4];
    const float* beta_z  = (const float*)d_in[5];
    const float* mean_z  = (const float*)d_in[6];
    const float* var_z   = (const float*)d_in[7];
    const float* gamma_x = (const float*)d_in[8];
    const float* beta_x  = (const float*)d_in[9];
    const float* mean_x  = (const float*)d_in[10];
    const float* var_x   = (const float*)d_in[11];
    float* out = (float*)d_out;

    float *zf, *xf;
    cudaGetSymbolAddress((void**)&zf, g_zf);
    cudaGetSymbolAddress((void**)&xf, g_xf);

    constexpr int SMEM_BYTES = 8 * 10240;   // 81920

    static bool attr_done = false;
    if (!attr_done) {
        cudaFuncSetAttribute(conv3x3_bn_wmma<14, 14, 16, 16>,
                             cudaFuncAttributeMaxDynamicSharedMemorySize, SMEM_BYTES);
        cudaFuncSetAttribute(conv3x3_bn_wmma<30, 30, 32, 32>,
                             cudaFuncAttributeMaxDynamicSharedMemorySize, SMEM_BYTES);
        attr_done = true;
    }

    // z branch: N = 12544 = 98 * 128
    conv3x3_bn_wmma<14, 14, 16, 16><<<dim3(98, 2), 256, SMEM_BYTES>>>(
        z, w_z, gamma_z, beta_z, mean_z, var_z, zf);

    // x branch: N = 57600 = 450 * 128
    conv3x3_bn_wmma<30, 30, 32, 32><<<dim3(450, 2), 256, SMEM_BYTES>>>(
        x, w_x, gamma_x, beta_x, mean_x, var_x, xf);

    // xcorr: 64*256*17 threads
    xcorr_kernel<<<1088, 256>>>(zf, xf, out);
}

// round 4
// speedup vs baseline: 1.6388x; 1.1759x over previous
#include <cuda_runtime.h>
#include <cuda_bf16.h>
#include <mma.h>
#include <cstdint>

using namespace nvcuda;

#define EPS 1e-5f

// Scratch (no cudaMalloc allowed).
__device__ __align__(16) float    g_zf[64 * 256 * 14 * 14];     // 12.8 MB
__device__ __align__(16) float    g_xf[64 * 256 * 30 * 30];     // 59 MB
__device__ __align__(16) uint32_t g_zp[64 * 256 * 16 * 16];     // 16.8 MB packed z
__device__ __align__(16) uint32_t g_xp[64 * 256 * 32 * 32];     // 67 MB packed x
__device__ __align__(16) uint32_t g_wzp[256 * 2304];            // 2.3 MB packed w_z
__device__ __align__(16) uint32_t g_wxp[256 * 2304];            // 2.3 MB packed w_x

__device__ __forceinline__ uint32_t prmt(uint32_t a, uint32_t b, uint32_t sel) {
    uint32_t r;
    asm("prmt.b32 %0, %1, %2, %3;" : "=r"(r) : "r"(a), "r"(b), "r"(sel));
    return r;
}

__device__ __forceinline__ uint32_t pack_hilo1(float v) {
    __nv_bfloat16 h = __float2bfloat16(v);
    __nv_bfloat16 l = __float2bfloat16(v - __bfloat162float(h));
    return (uint32_t)__bfloat16_as_ushort(h) |
           ((uint32_t)__bfloat16_as_ushort(l) << 16);
}

// ---------------------------------------------------------------------------
// One-time pack: fp32 -> u32 (bf16 hi | bf16 lo << 16), vectorized x4.
// ---------------------------------------------------------------------------
__global__ void pack_hilo_kernel(const float4* __restrict__ src,
                                 uint4* __restrict__ dst, int n4)
{
    int i = blockIdx.x * blockDim.x + threadIdx.x;
    if (i >= n4) return;
    float4 v = __ldg(src + i);
    uint4 o;
    o.x = pack_hilo1(v.x);
    o.y = pack_hilo1(v.y);
    o.z = pack_hilo1(v.z);
    o.w = pack_hilo1(v.w);
    dst[i] = o;
}

// ===========================================================================
// Implicit-GEMM 3x3 conv + fused BN, bf16 wmma 3-split from packed hi/lo.
// BM=128, BN=64, BK=32, 256 threads, 8 warps, warp tile 32x32 (acc 32 regs).
// Double-buffered SMEM; fill = LDG.u32 + PRMT only.
// ===========================================================================
template <int OH, int OW, int IH, int IW>
__global__ __launch_bounds__(256, 2)
void conv3x3_bn_wmma(const uint32_t* __restrict__ xp,   // packed input
                     const uint32_t* __restrict__ wp,   // packed weights [256,2304]
                     const float* __restrict__ gamma,
                     const float* __restrict__ beta,
                     const float* __restrict__ mean,
                     const float* __restrict__ var,
                     float* __restrict__ out)           // [B,256,OH,OW]
{
    constexpr int C = 256, K = C * 9;
    constexpr int BM = 128, BN = 64, BK = 32;
    constexpr int NCH = K / BK;           // 72
    constexpr int OHW = OH * OW;
    constexpr int LDA = 40;               // bf16 elems/row (80 B, 16B-mult)
    constexpr int LDC = 68;               // fp32 elems/row (272 B)
    // SMEM layout (bytes):
    //  A_hi: 2 x 10240, A_lo: 2 x 10240, B_hi: 2 x 5120, B_lo: 2 x 5120
    constexpr uint32_t A_T = BM * LDA * 2;      // 10240
    constexpr uint32_t B_T = BN * LDA * 2;      // 5120
    constexpr uint32_t OF_ALO = 2 * A_T;        // 20480
    constexpr uint32_t OF_BHI = 4 * A_T;        // 40960
    constexpr uint32_t OF_BLO = OF_BHI + 2 * B_T;

    extern __shared__ char smem[];

    const int tid = threadIdx.x;
    const int wid = tid >> 5;
    const int m0 = blockIdx.y * BM;
    const int n0 = blockIdx.x * BN;
    const int wm = (wid >> 1) * 32;       // 4 m-warps
    const int wn = (wid & 1) * 32;        // 2 n-warps

    // --- fill mappings ---
    const int arow  = tid >> 1;           // 0..127
    const int akoff = (tid & 1) * 16;
    const uint32_t* wr = wp + (size_t)(m0 + arow) * K + akoff;

    const int n_loc = tid & 63;
    const int koff  = (tid >> 6) * 8;     // 0,8,16,24
    const int n     = n0 + n_loc;
    const int b_    = n / OHW;
    const int rem   = n - b_ * OHW;
    const int ohh   = rem / OW;
    const int oww   = rem - ohh * OW;
    const uint32_t* xb = xp + (size_t)b_ * C * IH * IW + (size_t)ohh * IW + oww;

    auto fill = [&](int ch) {
        const int buf = ch & 1;
        // ---- A: 16 packed u32 (4 uint4), split -> 8 hi + 8 lo u32 ----
        {
            const uint4* src = reinterpret_cast<const uint4*>(wr + ch * BK);
            uint32_t* dh = (uint32_t*)(smem + buf * A_T) + arow * 20 + (akoff >> 1);
            uint32_t* dl = (uint32_t*)(smem + OF_ALO + buf * A_T) + arow * 20 + (akoff >> 1);
            uint32_t hi[8], lo[8];
#pragma unroll
            for (int i = 0; i < 4; i++) {
                uint4 v = __ldg(src + i);
                hi[i * 2 + 0] = prmt(v.x, v.y, 0x5410);
                lo[i * 2 + 0] = prmt(v.x, v.y, 0x7632);
                hi[i * 2 + 1] = prmt(v.z, v.w, 0x5410);
                lo[i * 2 + 1] = prmt(v.z, v.w, 0x7632);
            }
            *reinterpret_cast<uint4*>(dh + 0) = make_uint4(hi[0], hi[1], hi[2], hi[3]);
            *reinterpret_cast<uint4*>(dh + 4) = make_uint4(hi[4], hi[5], hi[6], hi[7]);
            *reinterpret_cast<uint4*>(dl + 0) = make_uint4(lo[0], lo[1], lo[2], lo[3]);
            *reinterpret_cast<uint4*>(dl + 4) = make_uint4(lo[4], lo[5], lo[6], lo[7]);
        }
        // ---- B: 8 gathered packed u32 -> 4 hi + 4 lo ----
        {
            int kg = ch * BK + koff;
            int ci = kg / 9;
            int r9 = kg - ci * 9;
            int kh = r9 / 3;
            int kw = r9 - kh * 3;
            uint32_t v[8];
#pragma unroll
            for (int j = 0; j < 8; j++) {
                v[j] = __ldg(xb + (ci * IH + kh) * IW + kw);
                kw++; if (kw == 3) { kw = 0; kh++; if (kh == 3) { kh = 0; ci++; } }
            }
            uint32_t* dh = (uint32_t*)(smem + OF_BHI + buf * B_T) + n_loc * 20 + (koff >> 1);
            uint32_t* dl = (uint32_t*)(smem + OF_BLO + buf * B_T) + n_loc * 20 + (koff >> 1);
            *reinterpret_cast<uint4*>(dh) = make_uint4(
                prmt(v[0], v[1], 0x5410), prmt(v[2], v[3], 0x5410),
                prmt(v[4], v[5], 0x5410), prmt(v[6], v[7], 0x5410));
            *reinterpret_cast<uint4*>(dl) = make_uint4(
                prmt(v[0], v[1], 0x7632), prmt(v[2], v[3], 0x7632),
                prmt(v[4], v[5], 0x7632), prmt(v[6], v[7], 0x7632));
        }
    };

    wmma::fragment<wmma::accumulator, 16, 16, 16, float> acc[2][2];
#pragma unroll
    for (int i = 0; i < 2; i++)
#pragma unroll
        for (int j = 0; j < 2; j++) wmma::fill_fragment(acc[i][j], 0.0f);

    fill(0);

#pragma unroll 1
    for (int ch = 0; ch < NCH; ch++) {
        __syncthreads();
        if (ch + 1 < NCH) fill(ch + 1);

        const int buf = ch & 1;
        const __nv_bfloat16* sa_hi = (const __nv_bfloat16*)(smem + buf * A_T);
        const __nv_bfloat16* sa_lo = (const __nv_bfloat16*)(smem + OF_ALO + buf * A_T);
        const __nv_bfloat16* sb_hi = (const __nv_bfloat16*)(smem + OF_BHI + buf * B_T);
        const __nv_bfloat16* sb_lo = (const __nv_bfloat16*)(smem + OF_BLO + buf * B_T);

#pragma unroll
        for (int ks = 0; ks < 2; ks++) {
            const int ko = ks * 16;
            wmma::fragment<wmma::matrix_a, 16, 16, 16, __nv_bfloat16, wmma::row_major> ah[2], al[2];
            wmma::fragment<wmma::matrix_b, 16, 16, 16, __nv_bfloat16, wmma::col_major> bh[2], bl[2];
#pragma unroll
            for (int i = 0; i < 2; i++) {
                wmma::load_matrix_sync(ah[i], sa_hi + (wm + i * 16) * LDA + ko, LDA);
                wmma::load_matrix_sync(al[i], sa_lo + (wm + i * 16) * LDA + ko, LDA);
            }
#pragma unroll
            for (int j = 0; j < 2; j++) {
                wmma::load_matrix_sync(bh[j], sb_hi + (wn + j * 16) * LDA + ko, LDA);
                wmma::load_matrix_sync(bl[j], sb_lo + (wn + j * 16) * LDA + ko, LDA);
            }
#pragma unroll
            for (int i = 0; i < 2; i++)
#pragma unroll
                for (int j = 0; j < 2; j++) {
                    wmma::mma_sync(acc[i][j], ah[i], bh[j], acc[i][j]);
                    wmma::mma_sync(acc[i][j], ah[i], bl[j], acc[i][j]);
                    wmma::mma_sync(acc[i][j], al[i], bh[j], acc[i][j]);
                }
        }
    }

    // ---- epilogue: acc -> SMEM C tile -> BN -> NCHW scatter ----
    __syncthreads();
    float* ct = (float*)smem;              // 128 x 68 fp32 = 34816 B
#pragma unroll
    for (int i = 0; i < 2; i++)
#pragma unroll
        for (int j = 0; j < 2; j++)
            wmma::store_matrix_sync(ct + (wm + i * 16) * LDC + wn + j * 16,
                                    acc[i][j], LDC, wmma::mem_row_major);
    __syncthreads();

#pragma unroll 1
    for (int it = 0; it < 32; it++) {
        const int idx = tid + it * 256;
        const int m = idx >> 6;
        const int nl = idx & 63;
        const int c = m0 + m;
        const float sc = __ldg(&gamma[c]) * rsqrtf(__ldg(&var[c]) + EPS);
        const float bi = __ldg(&beta[c]) - __ldg(&mean[c]) * sc;
        const int nn = n0 + nl;
        const int b2 = nn / OHW;
        const int s  = nn - b2 * OHW;
        out[((size_t)b2 * C + c) * OHW + s] = ct[m * LDC + nl] * sc + bi;
    }
}

// ===========================================================================
// Depthwise cross-correlation (FMA-bound, ~registers only).
// ===========================================================================
__global__ __launch_bounds__(256)
void xcorr_kernel(const float* __restrict__ zf,   // [BC,14,14]
                  const float* __restrict__ xf,   // [BC,30,30]
                  float* __restrict__ out)        // [BC,17,17]
{
    int g = blockIdx.x * blockDim.x + threadIdx.x;
    if (g >= 64 * 256 * 17) return;
    int oh = g % 17;
    int bc = g / 17;

    const float* zp = zf + bc * 196;
    const float* xp = xf + bc * 900;

    float acc[17];
#pragma unroll
    for (int j = 0; j < 17; j++) acc[j] = 0.f;

#pragma unroll 1
    for (int p = 0; p < 14; p++) {
        const float* row = xp + (oh + p) * 30;
        float xr[30];
#pragma unroll
        for (int t = 0; t < 30; t++) xr[t] = __ldg(row + t);
#pragma unroll
        for (int q = 0; q < 14; q++) {
            float zv = __ldg(zp + p * 14 + q);
#pragma unroll
            for (int j = 0; j < 17; j++)
                acc[j] = fmaf(zv, xr[q + j], acc[j]);
        }
    }

    float* op = out + bc * 289 + oh * 17;
#pragma unroll
    for (int j = 0; j < 17; j++) op[j] = acc[j];
}

// ===========================================================================
extern "C" void kernel_launch(void* const* d_in, const int* in_sizes, int n_in,
                              void* d_out, int out_size)
{
    const float* z       = (const float*)d_in[0];
    const float* x       = (const float*)d_in[1];
    const float* w_z     = (const float*)d_in[2];
    const float* w_x     = (const float*)d_in[3];
    const float* gamma_z = (const float*)d_in[4];
    const float* beta_z  = (const float*)d_in[5];
    const float* mean_z  = (const float*)d_in[6];
    const float* var_z   = (const float*)d_in[7];
    const float* gamma_x = (const float*)d_in[8];
    const float* beta_x  = (const float*)d_in[9];
    const float* mean_x  = (const float*)d_in[10];
    const float* var_x   = (const float*)d_in[11];
    float* out = (float*)d_out;

    float *zf, *xf;
    uint32_t *zp, *xp2, *wzp, *wxp;
    cudaGetSymbolAddress((void**)&zf, g_zf);
    cudaGetSymbolAddress((void**)&xf, g_xf);
    cudaGetSymbolAddress((void**)&zp, g_zp);
    cudaGetSymbolAddress((void**)&xp2, g_xp);
    cudaGetSymbolAddress((void**)&wzp, g_wzp);
    cudaGetSymbolAddress((void**)&wxp, g_wxp);

    constexpr int SMEM_BYTES = 61440;

    static bool attr_done = false;
    if (!attr_done) {
        cudaFuncSetAttribute(conv3x3_bn_wmma<14, 14, 16, 16>,
                             cudaFuncAttributeMaxDynamicSharedMemorySize, SMEM_BYTES);
        cudaFuncSetAttribute(conv3x3_bn_wmma<30, 30, 32, 32>,
                             cudaFuncAttributeMaxDynamicSharedMemorySize, SMEM_BYTES);
        attr_done = true;
    }

    // ---- pack inputs + weights to bf16 hi/lo (u32 per element) ----
    {
        int n4;
        n4 = 64 * 256 * 16 * 16 / 4;
        pack_hilo_kernel<<<(n4 + 255) / 256, 256>>>((const float4*)z, (uint4*)zp, n4);
        n4 = 64 * 256 * 32 * 32 / 4;
        pack_hilo_kernel<<<(n4 + 255) / 256, 256>>>((const float4*)x, (uint4*)xp2, n4);
        n4 = 256 * 2304 / 4;
        pack_hilo_kernel<<<(n4 + 255) / 256, 256>>>((const float4*)w_z, (uint4*)wzp, n4);
        pack_hilo_kernel<<<(n4 + 255) / 256, 256>>>((const float4*)w_x, (uint4*)wxp, n4);
    }

    // z branch: N = 12544 = 196 * 64
    conv3x3_bn_wmma<14, 14, 16, 16><<<dim3(196, 2), 256, SMEM_BYTES>>>(
        zp, wzp, gamma_z, beta_z, mean_z, var_z, zf);

    // x branch: N = 57600 = 900 * 64
    conv3x3_bn_wmma<30, 30, 32, 32><<<dim3(900, 2), 256, SMEM_BYTES>>>(
        xp2, wxp, gamma_x, beta_x, mean_x, var_x, xf);

    // xcorr
    xcorr_kernel<<<1088, 256>>>(zf, xf, out);
}

// round 5
// speedup vs baseline: 2.1212x; 1.2943x over previous
#include <cuda_runtime.h>
#include <cuda_bf16.h>
#include <mma.h>
#include <cstdint>

using namespace nvcuda;

#define EPS 1e-5f

// Scratch (no cudaMalloc allowed).
__device__ __align__(16) float    g_zf[64 * 256 * 14 * 14];     // 12.8 MB
__device__ __align__(16) float    g_xf[64 * 256 * 30 * 30];     // 59 MB
__device__ __align__(16) uint32_t g_zp[64 * 256 * 16 * 16];     // packed z (hi|lo)
__device__ __align__(16) uint32_t g_xp[64 * 256 * 32 * 32];     // packed x (hi|lo)
__device__ __align__(16) __nv_bfloat16 g_wz_hi[256 * 2304];     // weight hi plane
__device__ __align__(16) __nv_bfloat16 g_wz_lo[256 * 2304];
__device__ __align__(16) __nv_bfloat16 g_wx_hi[256 * 2304];
__device__ __align__(16) __nv_bfloat16 g_wx_lo[256 * 2304];

__device__ __forceinline__ uint32_t prmt(uint32_t a, uint32_t b, uint32_t sel) {
    uint32_t r;
    asm("prmt.b32 %0, %1, %2, %3;" : "=r"(r) : "r"(a), "r"(b), "r"(sel));
    return r;
}

__device__ __forceinline__ uint32_t smem_u32(const void* p) {
    uint32_t a;
    asm("{ .reg .u64 t; cvta.to.shared.u64 t, %1; cvt.u32.u64 %0, t; }"
        : "=r"(a) : "l"(p));
    return a;
}

#define CP_ASYNC16(dst, src) \
    asm volatile("cp.async.cg.shared.global [%0], [%1], 16;" \
        :: "r"(dst), "l"(src) : "memory")
#define CP_COMMIT() asm volatile("cp.async.commit_group;" ::: "memory")
#define CP_WAIT0()  asm volatile("cp.async.wait_group 0;" ::: "memory")

__device__ __forceinline__ uint32_t pack_hilo1(float v) {
    __nv_bfloat16 h = __float2bfloat16(v);
    __nv_bfloat16 l = __float2bfloat16(v - __bfloat162float(h));
    return (uint32_t)__bfloat16_as_ushort(h) |
           ((uint32_t)__bfloat16_as_ushort(l) << 16);
}

// ---- pack inputs: fp32 -> u32 (bf16 hi | bf16 lo<<16) ----
__global__ void pack_hilo_kernel(const float4* __restrict__ src,
                                 uint4* __restrict__ dst, int n4)
{
    int i = blockIdx.x * blockDim.x + threadIdx.x;
    if (i >= n4) return;
    float4 v = __ldg(src + i);
    uint4 o;
    o.x = pack_hilo1(v.x);
    o.y = pack_hilo1(v.y);
    o.z = pack_hilo1(v.z);
    o.w = pack_hilo1(v.w);
    dst[i] = o;
}

// ---- pack weights: fp32 -> separate hi / lo bf16 planes ----
__global__ void pack_planes_kernel(const float4* __restrict__ src,
                                   uint2* __restrict__ hi,
                                   uint2* __restrict__ lo, int n4)
{
    int i = blockIdx.x * blockDim.x + threadIdx.x;
    if (i >= n4) return;
    float4 v = __ldg(src + i);
    uint32_t px = pack_hilo1(v.x), py = pack_hilo1(v.y);
    uint32_t pz = pack_hilo1(v.z), pw = pack_hilo1(v.w);
    hi[i] = make_uint2(prmt(px, py, 0x5410), prmt(pz, pw, 0x5410));
    lo[i] = make_uint2(prmt(px, py, 0x7632), prmt(pz, pw, 0x7632));
}

// ===========================================================================
// Implicit-GEMM 3x3 conv + fused BN, bf16 wmma 3-split.
// BM=128, BN=64, BK=32, 256 threads, warp tile 32x32, 2 CTAs/SM.
// A (weights): pre-split planes, cp.async (zero-register fill, hidden 1 iter).
// B (im2col): packed u32 LDG prefetched into regs across the MMA block.
// ===========================================================================
template <int OH, int OW, int IH, int IW>
__global__ __launch_bounds__(256, 2)
void conv3x3_bn_wmma(const uint32_t* __restrict__ xp,       // packed input
                     const __nv_bfloat16* __restrict__ whi, // weight hi plane
                     const __nv_bfloat16* __restrict__ wlo, // weight lo plane
                     const float* __restrict__ gamma,
                     const float* __restrict__ beta,
                     const float* __restrict__ mean,
                     const float* __restrict__ var,
                     float* __restrict__ out)               // [B,256,OH,OW]
{
    constexpr int C = 256, K = C * 9;
    constexpr int BM = 128, BN = 64, BK = 32;
    constexpr int NCH = K / BK;           // 72
    constexpr int OHW = OH * OW;
    constexpr int LDA = 40;               // bf16 elems/row (80 B)
    constexpr int LDC = 68;
    constexpr uint32_t A_T = BM * LDA * 2;      // 10240
    constexpr uint32_t B_T = BN * LDA * 2;      // 5120
    constexpr uint32_t OF_ALO = 2 * A_T;        // 20480
    constexpr uint32_t OF_BHI = 4 * A_T;        // 40960
    constexpr uint32_t OF_BLO = OF_BHI + 2 * B_T;

    extern __shared__ char smem[];
    const uint32_t sbase = smem_u32(smem);

    const int tid = threadIdx.x;
    const int wid = tid >> 5;
    const int m0 = blockIdx.y * BM;
    const int n0 = blockIdx.x * BN;
    const int wm = (wid >> 1) * 32;
    const int wn = (wid & 1) * 32;

    // --- A fill mapping (cp.async): 2 chunks x 2 planes, 16B each ---
    // chunk c = tid + i*256 : row m = c>>2, k-quarter q = c&3 (8 bf16)
    const int am0 = (tid + 0)   >> 2, aq0 = (tid + 0)   & 3;
    const int am1 = (tid + 256) >> 2, aq1 = (tid + 256) & 3;
    const __nv_bfloat16* wh0 = whi + (size_t)(m0 + am0) * K + aq0 * 8;
    const __nv_bfloat16* wh1 = whi + (size_t)(m0 + am1) * K + aq1 * 8;
    const __nv_bfloat16* wl0 = wlo + (size_t)(m0 + am0) * K + aq0 * 8;
    const __nv_bfloat16* wl1 = wlo + (size_t)(m0 + am1) * K + aq1 * 8;
    const uint32_t ad0 = (uint32_t)(am0 * 80 + aq0 * 16);
    const uint32_t ad1 = (uint32_t)(am1 * 80 + aq1 * 16);

    // --- B fill mapping: one n, 8 k's per thread ---
    const int n_loc = tid & 63;
    const int koff  = (tid >> 6) * 8;     // 0,8,16,24
    const int n     = n0 + n_loc;
    const int b_    = n / OHW;
    const int rem   = n - b_ * OHW;
    const int ohh   = rem / OW;
    const int oww   = rem - ohh * OW;
    const uint32_t* xb = xp + (size_t)b_ * C * IH * IW + (size_t)ohh * IW + oww;

    auto fillA = [&](int ch) {
        const uint32_t buf = (uint32_t)(ch & 1);
        const uint32_t hi_s = sbase + buf * A_T;
        const uint32_t lo_s = sbase + OF_ALO + buf * A_T;
        const int ko = ch * BK;
        CP_ASYNC16(hi_s + ad0, wh0 + ko);
        CP_ASYNC16(hi_s + ad1, wh1 + ko);
        CP_ASYNC16(lo_s + ad0, wl0 + ko);
        CP_ASYNC16(lo_s + ad1, wl1 + ko);
    };

    auto ldgB = [&](int ch, uint32_t* v) {
        int kg = ch * BK + koff;
        int ci = kg / 9;
        int r9 = kg - ci * 9;
        int kh = r9 / 3;
        int kw = r9 - kh * 3;
#pragma unroll
        for (int j = 0; j < 8; j++) {
            v[j] = __ldg(xb + (ci * IH + kh) * IW + kw);
            kw++; if (kw == 3) { kw = 0; kh++; if (kh == 3) { kh = 0; ci++; } }
        }
    };
    auto stsB = [&](int ch, const uint32_t* v) {
        const int buf = ch & 1;
        uint32_t* dh = (uint32_t*)(smem + OF_BHI + buf * B_T) + n_loc * 20 + (koff >> 1);
        uint32_t* dl = (uint32_t*)(smem + OF_BLO + buf * B_T) + n_loc * 20 + (koff >> 1);
        *reinterpret_cast<uint4*>(dh) = make_uint4(
            prmt(v[0], v[1], 0x5410), prmt(v[2], v[3], 0x5410),
            prmt(v[4], v[5], 0x5410), prmt(v[6], v[7], 0x5410));
        *reinterpret_cast<uint4*>(dl) = make_uint4(
            prmt(v[0], v[1], 0x7632), prmt(v[2], v[3], 0x7632),
            prmt(v[4], v[5], 0x7632), prmt(v[6], v[7], 0x7632));
    };

    wmma::fragment<wmma::accumulator, 16, 16, 16, float> acc[2][2];
#pragma unroll
    for (int i = 0; i < 2; i++)
#pragma unroll
        for (int j = 0; j < 2; j++) wmma::fill_fragment(acc[i][j], 0.0f);

    // prologue: stage 0
    fillA(0);
    CP_COMMIT();
    {
        uint32_t v[8];
        ldgB(0, v);
        stsB(0, v);
    }

#pragma unroll 1
    for (int ch = 0; ch < NCH; ch++) {
        CP_WAIT0();
        __syncthreads();

        uint32_t v[8];
        const bool more = (ch + 1 < NCH);
        if (more) {
            fillA(ch + 1);
            CP_COMMIT();
            ldgB(ch + 1, v);           // LDGs in flight during MMA below
        }

        const int buf = ch & 1;
        const __nv_bfloat16* sa_hi = (const __nv_bfloat16*)(smem + buf * A_T);
        const __nv_bfloat16* sa_lo = (const __nv_bfloat16*)(smem + OF_ALO + buf * A_T);
        const __nv_bfloat16* sb_hi = (const __nv_bfloat16*)(smem + OF_BHI + buf * B_T);
        const __nv_bfloat16* sb_lo = (const __nv_bfloat16*)(smem + OF_BLO + buf * B_T);

#pragma unroll
        for (int ks = 0; ks < 2; ks++) {
            const int ko = ks * 16;
            wmma::fragment<wmma::matrix_a, 16, 16, 16, __nv_bfloat16, wmma::row_major> ah[2], al[2];
            wmma::fragment<wmma::matrix_b, 16, 16, 16, __nv_bfloat16, wmma::col_major> bh[2], bl[2];
#pragma unroll
            for (int i = 0; i < 2; i++) {
                wmma::load_matrix_sync(ah[i], sa_hi + (wm + i * 16) * LDA + ko, LDA);
                wmma::load_matrix_sync(al[i], sa_lo + (wm + i * 16) * LDA + ko, LDA);
            }
#pragma unroll
            for (int j = 0; j < 2; j++) {
                wmma::load_matrix_sync(bh[j], sb_hi + (wn + j * 16) * LDA + ko, LDA);
                wmma::load_matrix_sync(bl[j], sb_lo + (wn + j * 16) * LDA + ko, LDA);
            }
#pragma unroll
            for (int i = 0; i < 2; i++)
#pragma unroll
                for (int j = 0; j < 2; j++) {
                    wmma::mma_sync(acc[i][j], ah[i], bh[j], acc[i][j]);
                    wmma::mma_sync(acc[i][j], ah[i], bl[j], acc[i][j]);
                    wmma::mma_sync(acc[i][j], al[i], bh[j], acc[i][j]);
                }
        }

        if (more) stsB(ch + 1, v);     // after MMA: LDG latency covered
    }

    // ---- epilogue: acc -> SMEM C tile -> BN -> NCHW scatter ----
    __syncthreads();
    float* ct = (float*)smem;
#pragma unroll
    for (int i = 0; i < 2; i++)
#pragma unroll
        for (int j = 0; j < 2; j++)
            wmma::store_matrix_sync(ct + (wm + i * 16) * LDC + wn + j * 16,
                                    acc[i][j], LDC, wmma::mem_row_major);
    __syncthreads();

#pragma unroll 1
    for (int it = 0; it < 32; it++) {
        const int idx = tid + it * 256;
        const int m = idx >> 6;
        const int nl = idx & 63;
        const int c = m0 + m;
        const float sc = __ldg(&gamma[c]) * rsqrtf(__ldg(&var[c]) + EPS);
        const float bi = __ldg(&beta[c]) - __ldg(&mean[c]) * sc;
        const int nn = n0 + nl;
        const int b2 = nn / OHW;
        const int s  = nn - b2 * OHW;
        out[((size_t)b2 * C + c) * OHW + s] = ct[m * LDC + nl] * sc + bi;
    }
}

// ===========================================================================
// Depthwise cross-correlation.
// ===========================================================================
__global__ __launch_bounds__(256)
void xcorr_kernel(const float* __restrict__ zf,   // [BC,14,14]
                  const float* __restrict__ xf,   // [BC,30,30]
                  float* __restrict__ out)        // [BC,17,17]
{
    int g = blockIdx.x * blockDim.x + threadIdx.x;
    if (g >= 64 * 256 * 17) return;
    int oh = g % 17;
    int bc = g / 17;

    const float* zp = zf + bc * 196;
    const float* xp = xf + bc * 900;

    float acc[17];
#pragma unroll
    for (int j = 0; j < 17; j++) acc[j] = 0.f;

#pragma unroll 1
    for (int p = 0; p < 14; p++) {
        const float* row = xp + (oh + p) * 30;
        float xr[30];
#pragma unroll
        for (int t = 0; t < 30; t++) xr[t] = __ldg(row + t);
#pragma unroll
        for (int q = 0; q < 14; q++) {
            float zv = __ldg(zp + p * 14 + q);
#pragma unroll
            for (int j = 0; j < 17; j++)
                acc[j] = fmaf(zv, xr[q + j], acc[j]);
        }
    }

    float* op = out + bc * 289 + oh * 17;
#pragma unroll
    for (int j = 0; j < 17; j++) op[j] = acc[j];
}

// ===========================================================================
extern "C" void kernel_launch(void* const* d_in, const int* in_sizes, int n_in,
                              void* d_out, int out_size)
{
    const float* z       = (const float*)d_in[0];
    const float* x       = (const float*)d_in[1];
    const float* w_z     = (const float*)d_in[2];
    const float* w_x     = (const float*)d_in[3];
    const float* gamma_z = (const float*)d_in[4];
    const float* beta_z  = (const float*)d_in[5];
    const float* mean_z  = (const float*)d_in[6];
    const float* var_z   = (const float*)d_in[7];
    const float* gamma_x = (const float*)d_in[8];
    const float* beta_x  = (const float*)d_in[9];
    const float* mean_x  = (const float*)d_in[10];
    const float* var_x   = (const float*)d_in[11];
    float* out = (float*)d_out;

    float *zf, *xf;
    uint32_t *zp, *xp2;
    __nv_bfloat16 *wzh, *wzl, *wxh, *wxl;
    cudaGetSymbolAddress((void**)&zf, g_zf);
    cudaGetSymbolAddress((void**)&xf, g_xf);
    cudaGetSymbolAddress((void**)&zp, g_zp);
    cudaGetSymbolAddress((void**)&xp2, g_xp);
    cudaGetSymbolAddress((void**)&wzh, g_wz_hi);
    cudaGetSymbolAddress((void**)&wzl, g_wz_lo);
    cudaGetSymbolAddress((void**)&wxh, g_wx_hi);
    cudaGetSymbolAddress((void**)&wxl, g_wx_lo);

    constexpr int SMEM_BYTES = 61440;

    static bool attr_done = false;
    if (!attr_done) {
        cudaFuncSetAttribute(conv3x3_bn_wmma<14, 14, 16, 16>,
                             cudaFuncAttributeMaxDynamicSharedMemorySize, SMEM_BYTES);
        cudaFuncSetAttribute(conv3x3_bn_wmma<30, 30, 32, 32>,
                             cudaFuncAttributeMaxDynamicSharedMemorySize, SMEM_BYTES);
        attr_done = true;
    }

    // ---- pack inputs (u32) + weights (hi/lo planes) ----
    {
        int n4;
        n4 = 64 * 256 * 16 * 16 / 4;
        pack_hilo_kernel<<<(n4 + 255) / 256, 256>>>((const float4*)z, (uint4*)zp, n4);
        n4 = 64 * 256 * 32 * 32 / 4;
        pack_hilo_kernel<<<(n4 + 255) / 256, 256>>>((const float4*)x, (uint4*)xp2, n4);
        n4 = 256 * 2304 / 4;
        pack_planes_kernel<<<(n4 + 255) / 256, 256>>>(
            (const float4*)w_z, (uint2*)wzh, (uint2*)wzl, n4);
        pack_planes_kernel<<<(n4 + 255) / 256, 256>>>(
            (const float4*)w_x, (uint2*)wxh, (uint2*)wxl, n4);
    }

    // z branch: N = 12544 = 196 * 64
    conv3x3_bn_wmma<14, 14, 16, 16><<<dim3(196, 2), 256, SMEM_BYTES>>>(
        zp, wzh, wzl, gamma_z, beta_z, mean_z, var_z, zf);

    // x branch: N = 57600 = 900 * 64
    conv3x3_bn_wmma<30, 30, 32, 32><<<dim3(900, 2), 256, SMEM_BYTES>>>(
        xp2, wxh, wxl, gamma_x, beta_x, mean_x, var_x, xf);

    // xcorr
    xcorr_kernel<<<1088, 256>>>(zf, xf, out);
}

// round 6
// speedup vs baseline: 2.2119x; 1.0428x over previous
#include <cuda_runtime.h>
#include <cuda_bf16.h>
#include <mma.h>
#include <cstdint>

using namespace nvcuda;

#define EPS 1e-5f

// Scratch (no cudaMalloc allowed).
__device__ __align__(16) float    g_zf[64 * 256 * 14 * 14];     // 12.8 MB
__device__ __align__(16) float    g_xf[64 * 256 * 30 * 30];     // 59 MB
__device__ __align__(16) uint32_t g_zp[64 * 256 * 16 * 16];     // packed z (hi|lo)
__device__ __align__(16) uint32_t g_xp[64 * 256 * 32 * 32];     // packed x (hi|lo)
__device__ __align__(16) __nv_bfloat16 g_wz_hi[256 * 2304];     // weight hi plane
__device__ __align__(16) __nv_bfloat16 g_wz_lo[256 * 2304];
__device__ __align__(16) __nv_bfloat16 g_wx_hi[256 * 2304];
__device__ __align__(16) __nv_bfloat16 g_wx_lo[256 * 2304];

__device__ __forceinline__ uint32_t prmt(uint32_t a, uint32_t b, uint32_t sel) {
    uint32_t r;
    asm("prmt.b32 %0, %1, %2, %3;" : "=r"(r) : "r"(a), "r"(b), "r"(sel));
    return r;
}

__device__ __forceinline__ uint32_t smem_u32(const void* p) {
    uint32_t a;
    asm("{ .reg .u64 t; cvta.to.shared.u64 t, %1; cvt.u32.u64 %0, t; }"
        : "=r"(a) : "l"(p));
    return a;
}

#define CP_ASYNC16(dst, src) \
    asm volatile("cp.async.cg.shared.global [%0], [%1], 16;" \
        :: "r"(dst), "l"(src) : "memory")
#define CP_COMMIT() asm volatile("cp.async.commit_group;" ::: "memory")
#define CP_WAIT0()  asm volatile("cp.async.wait_group 0;" ::: "memory")

__device__ __forceinline__ uint32_t pack_hilo1(float v) {
    __nv_bfloat16 h = __float2bfloat16(v);
    __nv_bfloat16 l = __float2bfloat16(v - __bfloat162float(h));
    return (uint32_t)__bfloat16_as_ushort(h) |
           ((uint32_t)__bfloat16_as_ushort(l) << 16);
}

// ---- pack inputs: fp32 -> u32 (bf16 hi | bf16 lo<<16) ----
__global__ void pack_hilo_kernel(const float4* __restrict__ src,
                                 uint4* __restrict__ dst, int n4)
{
    int i = blockIdx.x * blockDim.x + threadIdx.x;
    if (i >= n4) return;
    float4 v = __ldg(src + i);
    uint4 o;
    o.x = pack_hilo1(v.x);
    o.y = pack_hilo1(v.y);
    o.z = pack_hilo1(v.z);
    o.w = pack_hilo1(v.w);
    dst[i] = o;
}

// ---- pack weights: fp32 -> separate hi / lo bf16 planes ----
__global__ void pack_planes_kernel(const float4* __restrict__ src,
                                   uint2* __restrict__ hi,
                                   uint2* __restrict__ lo, int n4)
{
    int i = blockIdx.x * blockDim.x + threadIdx.x;
    if (i >= n4) return;
    float4 v = __ldg(src + i);
    uint32_t px = pack_hilo1(v.x), py = pack_hilo1(v.y);
    uint32_t pz = pack_hilo1(v.z), pw = pack_hilo1(v.w);
    hi[i] = make_uint2(prmt(px, py, 0x5410), prmt(pz, pw, 0x5410));
    lo[i] = make_uint2(prmt(px, py, 0x7632), prmt(pz, pw, 0x7632));
}

// ===========================================================================
// Implicit-GEMM 3x3 conv + fused BN, bf16 wmma 3-split.
// BM=128, BN=64, BK=64, 256 threads, warp tile 32x32, 2 CTAs/SM.
// 36 k-iterations (amortized barriers), cp.async A-fill, reg-staged B gather.
// ===========================================================================
template <int OH, int OW, int IH, int IW>
__global__ __launch_bounds__(256, 2)
void conv3x3_bn_wmma(const uint32_t* __restrict__ xp,       // packed input
                     const __nv_bfloat16* __restrict__ whi, // weight hi plane
                     const __nv_bfloat16* __restrict__ wlo, // weight lo plane
                     const float* __restrict__ gamma,
                     const float* __restrict__ beta,
                     const float* __restrict__ mean,
                     const float* __restrict__ var,
                     float* __restrict__ out)               // [B,256,OH,OW]
{
    constexpr int C = 256, K = C * 9;
    constexpr int BM = 128, BN = 64, BK = 64;
    constexpr int NCH = K / BK;                 // 36
    constexpr int OHW = OH * OW;
    constexpr int LDA = 72;                     // bf16 elems/row (144 B)
    constexpr int LDC = 68;
    constexpr uint32_t A_T = BM * LDA * 2;      // 18432
    constexpr uint32_t B_T = BN * LDA * 2;      // 9216
    constexpr uint32_t OF_ALO = 2 * A_T;        // 36864
    constexpr uint32_t OF_BHI = 4 * A_T;        // 73728
    constexpr uint32_t OF_BLO = OF_BHI + 2 * B_T;   // 92160
    // total smem = 110592

    extern __shared__ char smem[];
    const uint32_t sbase = smem_u32(smem);

    const int tid = threadIdx.x;
    const int wid = tid >> 5;
    const int m0 = blockIdx.y * BM;
    const int n0 = blockIdx.x * BN;
    const int wm = (wid >> 1) * 32;
    const int wn = (wid & 1) * 32;

    // --- A fill (cp.async): 4 chunks/plane, chunk i: row r0+32i, subchunk q ---
    const int r0 = tid >> 3;            // 0..31
    const int q  = tid & 7;             // 0..7  (16B = 8 bf16 along k)
    const __nv_bfloat16* whp = whi + (size_t)(m0 + r0) * K + q * 8;
    const __nv_bfloat16* wlp = wlo + (size_t)(m0 + r0) * K + q * 8;
    const uint32_t ad0 = (uint32_t)(r0 * 144 + q * 16);

    // --- B fill: one n, 16 k's per thread ---
    const int n_loc = tid & 63;
    const int koff  = (tid >> 6) * 16;  // 0,16,32,48
    const int n     = n0 + n_loc;
    const int b_    = n / OHW;
    const int rem   = n - b_ * OHW;
    const int ohh   = rem / OW;
    const int oww   = rem - ohh * OW;
    const uint32_t* xb = xp + (size_t)b_ * C * IH * IW + (size_t)ohh * IW + oww;

    auto fillA = [&](int ch) {
        const uint32_t buf = (uint32_t)(ch & 1);
        const uint32_t hi_s = sbase + buf * A_T + ad0;
        const uint32_t lo_s = sbase + OF_ALO + buf * A_T + ad0;
        const int ko = ch * BK;
#pragma unroll
        for (int i = 0; i < 4; i++) {
            CP_ASYNC16(hi_s + i * 4608u, whp + ko + (size_t)i * 32 * K);
            CP_ASYNC16(lo_s + i * 4608u, wlp + ko + (size_t)i * 32 * K);
        }
    };

    auto ldgB = [&](int ch, uint32_t* v) {
        int kg = ch * BK + koff;
        int ci = kg / 9;
        int r9 = kg - ci * 9;
        int kh = r9 / 3;
        int kw = r9 - kh * 3;
#pragma unroll
        for (int j = 0; j < 16; j++) {
            v[j] = __ldg(xb + (ci * IH + kh) * IW + kw);
            kw++; if (kw == 3) { kw = 0; kh++; if (kh == 3) { kh = 0; ci++; } }
        }
    };
    auto stsB = [&](int ch, const uint32_t* v) {
        const int buf = ch & 1;
        uint32_t* dh = (uint32_t*)(smem + OF_BHI + buf * B_T) + n_loc * 36 + (koff >> 1);
        uint32_t* dl = (uint32_t*)(smem + OF_BLO + buf * B_T) + n_loc * 36 + (koff >> 1);
#pragma unroll
        for (int h = 0; h < 2; h++) {
            const uint32_t* s = v + h * 8;
            *reinterpret_cast<uint4*>(dh + h * 4) = make_uint4(
                prmt(s[0], s[1], 0x5410), prmt(s[2], s[3], 0x5410),
                prmt(s[4], s[5], 0x5410), prmt(s[6], s[7], 0x5410));
            *reinterpret_cast<uint4*>(dl + h * 4) = make_uint4(
                prmt(s[0], s[1], 0x7632), prmt(s[2], s[3], 0x7632),
                prmt(s[4], s[5], 0x7632), prmt(s[6], s[7], 0x7632));
        }
    };

    wmma::fragment<wmma::accumulator, 16, 16, 16, float> acc[2][2];
#pragma unroll
    for (int i = 0; i < 2; i++)
#pragma unroll
        for (int j = 0; j < 2; j++) wmma::fill_fragment(acc[i][j], 0.0f);

    // prologue: stage 0
    fillA(0);
    CP_COMMIT();
    {
        uint32_t v[16];
        ldgB(0, v);
        stsB(0, v);
    }

#pragma unroll 1
    for (int ch = 0; ch < NCH; ch++) {
        CP_WAIT0();
        __syncthreads();

        uint32_t v[16];
        const bool more = (ch + 1 < NCH);
        if (more) {
            fillA(ch + 1);
            CP_COMMIT();
            ldgB(ch + 1, v);           // LDGs in flight during MMA below
        }

        const int buf = ch & 1;
        const __nv_bfloat16* sa_hi = (const __nv_bfloat16*)(smem + buf * A_T);
        const __nv_bfloat16* sa_lo = (const __nv_bfloat16*)(smem + OF_ALO + buf * A_T);
        const __nv_bfloat16* sb_hi = (const __nv_bfloat16*)(smem + OF_BHI + buf * B_T);
        const __nv_bfloat16* sb_lo = (const __nv_bfloat16*)(smem + OF_BLO + buf * B_T);

#pragma unroll
        for (int ks = 0; ks < 4; ks++) {
            const int ko = ks * 16;
            wmma::fragment<wmma::matrix_a, 16, 16, 16, __nv_bfloat16, wmma::row_major> ah[2], al[2];
            wmma::fragment<wmma::matrix_b, 16, 16, 16, __nv_bfloat16, wmma::col_major> bh[2], bl[2];
#pragma unroll
            for (int i = 0; i < 2; i++) {
                wmma::load_matrix_sync(ah[i], sa_hi + (wm + i * 16) * LDA + ko, LDA);
                wmma::load_matrix_sync(al[i], sa_lo + (wm + i * 16) * LDA + ko, LDA);
            }
#pragma unroll
            for (int j = 0; j < 2; j++) {
                wmma::load_matrix_sync(bh[j], sb_hi + (wn + j * 16) * LDA + ko, LDA);
                wmma::load_matrix_sync(bl[j], sb_lo + (wn + j * 16) * LDA + ko, LDA);
            }
#pragma unroll
            for (int i = 0; i < 2; i++)
#pragma unroll
                for (int j = 0; j < 2; j++) {
                    wmma::mma_sync(acc[i][j], ah[i], bh[j], acc[i][j]);
                    wmma::mma_sync(acc[i][j], ah[i], bl[j], acc[i][j]);
                    wmma::mma_sync(acc[i][j], al[i], bh[j], acc[i][j]);
                }
        }

        if (more) stsB(ch + 1, v);     // after MMA: LDG latency covered
    }

    // ---- epilogue: acc -> SMEM C tile -> BN -> NCHW scatter ----
    __syncthreads();
    float* ct = (float*)smem;
#pragma unroll
    for (int i = 0; i < 2; i++)
#pragma unroll
        for (int j = 0; j < 2; j++)
            wmma::store_matrix_sync(ct + (wm + i * 16) * LDC + wn + j * 16,
                                    acc[i][j], LDC, wmma::mem_row_major);
    __syncthreads();

#pragma unroll 1
    for (int it = 0; it < 32; it++) {
        const int idx = tid + it * 256;
        const int m = idx >> 6;
        const int nl = idx & 63;
        const int c = m0 + m;
        const float sc = __ldg(&gamma[c]) * rsqrtf(__ldg(&var[c]) + EPS);
        const float bi = __ldg(&beta[c]) - __ldg(&mean[c]) * sc;
        const int nn = n0 + nl;
        const int b2 = nn / OHW;
        const int s  = nn - b2 * OHW;
        out[((size_t)b2 * C + c) * OHW + s] = ct[m * LDC + nl] * sc + bi;
    }
}

// ===========================================================================
// Depthwise cross-correlation.
// ===========================================================================
__global__ __launch_bounds__(256)
void xcorr_kernel(const float* __restrict__ zf,   // [BC,14,14]
                  const float* __restrict__ xf,   // [BC,30,30]
                  float* __restrict__ out)        // [BC,17,17]
{
    int g = blockIdx.x * blockDim.x + threadIdx.x;
    if (g >= 64 * 256 * 17) return;
    int oh = g % 17;
    int bc = g / 17;

    const float* zp = zf + bc * 196;
    const float* xp = xf + bc * 900;

    float acc[17];
#pragma unroll
    for (int j = 0; j < 17; j++) acc[j] = 0.f;

#pragma unroll 1
    for (int p = 0; p < 14; p++) {
        const float* row = xp + (oh + p) * 30;
        float xr[30];
#pragma unroll
        for (int t = 0; t < 30; t++) xr[t] = __ldg(row + t);
#pragma unroll
        for (int q = 0; q < 14; q++) {
            float zv = __ldg(zp + p * 14 + q);
#pragma unroll
            for (int j = 0; j < 17; j++)
                acc[j] = fmaf(zv, xr[q + j], acc[j]);
        }
    }

    float* op = out + bc * 289 + oh * 17;
#pragma unroll
    for (int j = 0; j < 17; j++) op[j] = acc[j];
}

// ===========================================================================
extern "C" void kernel_launch(void* const* d_in, const int* in_sizes, int n_in,
                              void* d_out, int out_size)
{
    const float* z       = (const float*)d_in[0];
    const float* x       = (const float*)d_in[1];
    const float* w_z     = (const float*)d_in[2];
    const float* w_x     = (const float*)d_in[3];
    const float* gamma_z = (const float*)d_in[4];
    const float* beta_z  = (const float*)d_in[5];
    const float* mean_z  = (const float*)d_in[6];
    const float* var_z   = (const float*)d_in[7];
    const float* gamma_x = (const float*)d_in[8];
    const float* beta_x  = (const float*)d_in[9];
    const float* mean_x  = (const float*)d_in[10];
    const float* var_x   = (const float*)d_in[11];
    float* out = (float*)d_out;

    float *zf, *xf;
    uint32_t *zp, *xp2;
    __nv_bfloat16 *wzh, *wzl, *wxh, *wxl;
    cudaGetSymbolAddress((void**)&zf, g_zf);
    cudaGetSymbolAddress((void**)&xf, g_xf);
    cudaGetSymbolAddress((void**)&zp, g_zp);
    cudaGetSymbolAddress((void**)&xp2, g_xp);
    cudaGetSymbolAddress((void**)&wzh, g_wz_hi);
    cudaGetSymbolAddress((void**)&wzl, g_wz_lo);
    cudaGetSymbolAddress((void**)&wxh, g_wx_hi);
    cudaGetSymbolAddress((void**)&wxl, g_wx_lo);

    constexpr int SMEM_BYTES = 110592;

    static bool attr_done = false;
    if (!attr_done) {
        cudaFuncSetAttribute(conv3x3_bn_wmma<14, 14, 16, 16>,
                             cudaFuncAttributeMaxDynamicSharedMemorySize, SMEM_BYTES);
        cudaFuncSetAttribute(conv3x3_bn_wmma<30, 30, 32, 32>,
                             cudaFuncAttributeMaxDynamicSharedMemorySize, SMEM_BYTES);
        attr_done = true;
    }

    // ---- pack inputs (u32) + weights (hi/lo planes) ----
    {
        int n4;
        n4 = 64 * 256 * 16 * 16 / 4;
        pack_hilo_kernel<<<(n4 + 255) / 256, 256>>>((const float4*)z, (uint4*)zp, n4);
        n4 = 64 * 256 * 32 * 32 / 4;
        pack_hilo_kernel<<<(n4 + 255) / 256, 256>>>((const float4*)x, (uint4*)xp2, n4);
        n4 = 256 * 2304 / 4;
        pack_planes_kernel<<<(n4 + 255) / 256, 256>>>(
            (const float4*)w_z, (uint2*)wzh, (uint2*)wzl, n4);
        pack_planes_kernel<<<(n4 + 255) / 256, 256>>>(
            (const float4*)w_x, (uint2*)wxh, (uint2*)wxl, n4);
    }

    // z branch: N = 12544 = 196 * 64
    conv3x3_bn_wmma<14, 14, 16, 16><<<dim3(196, 2), 256, SMEM_BYTES>>>(
        zp, wzh, wzl, gamma_z, beta_z, mean_z, var_z, zf);

    // x branch: N = 57600 = 900 * 64
    conv3x3_bn_wmma<30, 30, 32, 32><<<dim3(900, 2), 256, SMEM_BYTES>>>(
        xp2, wxh, wxl, gamma_x, beta_x, mean_x, var_x, xf);

    // xcorr
    xcorr_kernel<<<1088, 256>>>(zf, xf, out);
}

// round 7
// speedup vs baseline: 3.4820x; 1.5742x over previous
#include <cuda_runtime.h>
#include <cuda_fp16.h>
#include <mma.h>
#include <cstdint>

using namespace nvcuda;

#define EPS 1e-5f

// Scratch (no cudaMalloc allowed).
__device__ __align__(16) float    g_zf[64 * 256 * 14 * 14];     // 12.8 MB
__device__ __align__(16) float    g_xf[64 * 256 * 30 * 30];     // 59 MB
__device__ __align__(16) uint32_t g_zp[64 * 256 * 16 * 16];     // packed z (fp16 hi|lo)
__device__ __align__(16) uint32_t g_xp[64 * 256 * 32 * 32];     // packed x (fp16 hi|lo)
__device__ __align__(16) __half   g_wz[256 * 2304];             // fp16 weights z
__device__ __align__(16) __half   g_wx[256 * 2304];             // fp16 weights x

__device__ __forceinline__ uint32_t prmt(uint32_t a, uint32_t b, uint32_t sel) {
    uint32_t r;
    asm("prmt.b32 %0, %1, %2, %3;" : "=r"(r) : "r"(a), "r"(b), "r"(sel));
    return r;
}

__device__ __forceinline__ uint32_t smem_u32(const void* p) {
    uint32_t a;
    asm("{ .reg .u64 t; cvta.to.shared.u64 t, %1; cvt.u32.u64 %0, t; }"
        : "=r"(a) : "l"(p));
    return a;
}

#define CP_ASYNC16(dst, src) \
    asm volatile("cp.async.cg.shared.global [%0], [%1], 16;" \
        :: "r"(dst), "l"(src) : "memory")
#define CP_COMMIT() asm volatile("cp.async.commit_group;" ::: "memory")
#define CP_WAIT0()  asm volatile("cp.async.wait_group 0;" ::: "memory")

// fp16 2-split pack: u32 = half(v) | half(v - half(v)) << 16
__device__ __forceinline__ uint32_t pack_h2(float v) {
    __half h = __float2half_rn(v);
    __half l = __float2half_rn(v - __half2float(h));
    return (uint32_t)__half_as_ushort(h) |
           ((uint32_t)__half_as_ushort(l) << 16);
}

// ---- pack inputs: fp32 -> u32 (fp16 hi | fp16 lo<<16) ----
__global__ void pack_in_kernel(const float4* __restrict__ src,
                               uint4* __restrict__ dst, int n4)
{
    int i = blockIdx.x * blockDim.x + threadIdx.x;
    if (i >= n4) return;
    float4 v = __ldg(src + i);
    dst[i] = make_uint4(pack_h2(v.x), pack_h2(v.y), pack_h2(v.z), pack_h2(v.w));
}

// ---- pack weights: fp32 -> single fp16 plane ----
__global__ void pack_w_kernel(const float4* __restrict__ src,
                              uint2* __restrict__ dst, int n4)
{
    int i = blockIdx.x * blockDim.x + threadIdx.x;
    if (i >= n4) return;
    float4 v = __ldg(src + i);
    __half2 h01 = __floats2half2_rn(v.x, v.y);
    __half2 h23 = __floats2half2_rn(v.z, v.w);
    dst[i] = make_uint2(*reinterpret_cast<uint32_t*>(&h01),
                        *reinterpret_cast<uint32_t*>(&h23));
}

// ===========================================================================
// Implicit-GEMM 3x3 conv + fused BN, fp16 wmma 2-split.
//   w*x ~= wh*xh + wh*xl  (weights single fp16, inputs split hi/lo)
// BM=128, BN=64, BK=64, 256 threads, warp tile 32x32, 2 CTAs/SM.
// ===========================================================================
template <int OH, int OW, int IH, int IW>
__global__ __launch_bounds__(256, 2)
void conv3x3_bn_wmma(const uint32_t* __restrict__ xp,   // packed input (hi|lo)
                     const __half* __restrict__ whalf,  // fp16 weights [256,2304]
                     const float* __restrict__ gamma,
                     const float* __restrict__ beta,
                     const float* __restrict__ mean,
                     const float* __restrict__ var,
                     float* __restrict__ out)           // [B,256,OH,OW]
{
    constexpr int C = 256, K = C * 9;
    constexpr int BM = 128, BN = 64, BK = 64;
    constexpr int NCH = K / BK;                 // 36
    constexpr int OHW = OH * OW;
    constexpr int LDA = 72;                     // fp16 elems/row (144 B)
    constexpr int LDC = 68;
    constexpr uint32_t A_T = BM * LDA * 2;      // 18432 (single plane)
    constexpr uint32_t B_T = BN * LDA * 2;      // 9216
    constexpr uint32_t OF_BHI = 2 * A_T;        // 36864
    constexpr uint32_t OF_BLO = OF_BHI + 2 * B_T;   // 55296
    // total smem = 73728

    extern __shared__ char smem[];
    const uint32_t sbase = smem_u32(smem);

    const int tid = threadIdx.x;
    const int wid = tid >> 5;
    const int m0 = blockIdx.y * BM;
    const int n0 = blockIdx.x * BN;
    const int wm = (wid >> 1) * 32;
    const int wn = (wid & 1) * 32;

    // --- A fill (cp.async): 4 chunks, chunk i: row r0+32i, 16B sub q ---
    const int r0 = tid >> 3;            // 0..31
    const int q  = tid & 7;             // 0..7  (16B = 8 fp16 along k)
    const __half* whp = whalf + (size_t)(m0 + r0) * K + q * 8;
    const uint32_t ad0 = (uint32_t)(r0 * 144 + q * 16);

    // --- B fill: one n, 16 k's per thread ---
    const int n_loc = tid & 63;
    const int koff  = (tid >> 6) * 16;  // 0,16,32,48
    const int n     = n0 + n_loc;
    const int b_    = n / OHW;
    const int rem   = n - b_ * OHW;
    const int ohh   = rem / OW;
    const int oww   = rem - ohh * OW;
    const uint32_t* xb = xp + (size_t)b_ * C * IH * IW + (size_t)ohh * IW + oww;

    auto fillA = [&](int ch) {
        const uint32_t s = sbase + (uint32_t)(ch & 1) * A_T + ad0;
        const int ko = ch * BK;
#pragma unroll
        for (int i = 0; i < 4; i++)
            CP_ASYNC16(s + i * 4608u, whp + ko + (size_t)i * 32 * K);
    };

    auto ldgB = [&](int ch, uint32_t* v) {
        int kg = ch * BK + koff;
        int ci = kg / 9;
        int r9 = kg - ci * 9;
        int kh = r9 / 3;
        int kw = r9 - kh * 3;
#pragma unroll
        for (int j = 0; j < 16; j++) {
            v[j] = __ldg(xb + (ci * IH + kh) * IW + kw);
            kw++; if (kw == 3) { kw = 0; kh++; if (kh == 3) { kh = 0; ci++; } }
        }
    };
    auto stsB = [&](int ch, const uint32_t* v) {
        const int buf = ch & 1;
        uint32_t* dh = (uint32_t*)(smem + OF_BHI + buf * B_T) + n_loc * 36 + (koff >> 1);
        uint32_t* dl = (uint32_t*)(smem + OF_BLO + buf * B_T) + n_loc * 36 + (koff >> 1);
#pragma unroll
        for (int h = 0; h < 2; h++) {
            const uint32_t* s = v + h * 8;
            *reinterpret_cast<uint4*>(dh + h * 4) = make_uint4(
                prmt(s[0], s[1], 0x5410), prmt(s[2], s[3], 0x5410),
                prmt(s[4], s[5], 0x5410), prmt(s[6], s[7], 0x5410));
            *reinterpret_cast<uint4*>(dl + h * 4) = make_uint4(
                prmt(s[0], s[1], 0x7632), prmt(s[2], s[3], 0x7632),
                prmt(s[4], s[5], 0x7632), prmt(s[6], s[7], 0x7632));
        }
    };

    wmma::fragment<wmma::accumulator, 16, 16, 16, float> acc[2][2];
#pragma unroll
    for (int i = 0; i < 2; i++)
#pragma unroll
        for (int j = 0; j < 2; j++) wmma::fill_fragment(acc[i][j], 0.0f);

    // prologue: stage 0
    fillA(0);
    CP_COMMIT();
    {
        uint32_t v[16];
        ldgB(0, v);
        stsB(0, v);
    }

#pragma unroll 1
    for (int ch = 0; ch < NCH; ch++) {
        CP_WAIT0();
        __syncthreads();

        uint32_t v[16];
        const bool more = (ch + 1 < NCH);
        if (more) {
            fillA(ch + 1);
            CP_COMMIT();
            ldgB(ch + 1, v);           // LDGs in flight during MMA below
        }

        const int buf = ch & 1;
        const __half* sa   = (const __half*)(smem + buf * A_T);
        const __half* sb_h = (const __half*)(smem + OF_BHI + buf * B_T);
        const __half* sb_l = (const __half*)(smem + OF_BLO + buf * B_T);

#pragma unroll
        for (int ks = 0; ks < 4; ks++) {
            const int ko = ks * 16;
            wmma::fragment<wmma::matrix_a, 16, 16, 16, __half, wmma::row_major> a[2];
            wmma::fragment<wmma::matrix_b, 16, 16, 16, __half, wmma::col_major> bh[2], bl[2];
#pragma unroll
            for (int i = 0; i < 2; i++)
                wmma::load_matrix_sync(a[i], sa + (wm + i * 16) * LDA + ko, LDA);
#pragma unroll
            for (int j = 0; j < 2; j++) {
                wmma::load_matrix_sync(bh[j], sb_h + (wn + j * 16) * LDA + ko, LDA);
                wmma::load_matrix_sync(bl[j], sb_l + (wn + j * 16) * LDA + ko, LDA);
            }
#pragma unroll
            for (int i = 0; i < 2; i++)
#pragma unroll
                for (int j = 0; j < 2; j++) {
                    wmma::mma_sync(acc[i][j], a[i], bh[j], acc[i][j]);
                    wmma::mma_sync(acc[i][j], a[i], bl[j], acc[i][j]);
                }
        }

        if (more) stsB(ch + 1, v);     // after MMA: LDG latency covered
    }

    // ---- epilogue: acc -> SMEM C tile -> BN -> NCHW scatter ----
    __syncthreads();
    float* ct = (float*)smem;
#pragma unroll
    for (int i = 0; i < 2; i++)
#pragma unroll
        for (int j = 0; j < 2; j++)
            wmma::store_matrix_sync(ct + (wm + i * 16) * LDC + wn + j * 16,
                                    acc[i][j], LDC, wmma::mem_row_major);
    __syncthreads();

#pragma unroll 1
    for (int it = 0; it < 32; it++) {
        const int idx = tid + it * 256;
        const int m = idx >> 6;
        const int nl = idx & 63;
        const int c = m0 + m;
        const float sc = __ldg(&gamma[c]) * rsqrtf(__ldg(&var[c]) + EPS);
        const float bi = __ldg(&beta[c]) - __ldg(&mean[c]) * sc;
        const int nn = n0 + nl;
        const int b2 = nn / OHW;
        const int s  = nn - b2 * OHW;
        out[((size_t)b2 * C + c) * OHW + s] = ct[m * LDC + nl] * sc + bi;
    }
}

// ===========================================================================
// Depthwise cross-correlation (float2-vectorized loads).
// ===========================================================================
__global__ __launch_bounds__(256)
void xcorr_kernel(const float* __restrict__ zf,   // [BC,14,14]
                  const float* __restrict__ xf,   // [BC,30,30]
                  float* __restrict__ out)        // [BC,17,17]
{
    int g = blockIdx.x * blockDim.x + threadIdx.x;
    if (g >= 64 * 256 * 17) return;
    int oh = g % 17;
    int bc = g / 17;

    const float* zp = zf + bc * 196;
    const float* xp = xf + bc * 900;

    float acc[17];
#pragma unroll
    for (int j = 0; j < 17; j++) acc[j] = 0.f;

#pragma unroll 1
    for (int p = 0; p < 14; p++) {
        const float2* row2 = reinterpret_cast<const float2*>(xp + (oh + p) * 30);
        float xr[30];
#pragma unroll
        for (int t = 0; t < 15; t++) {
            float2 u = __ldg(row2 + t);
            xr[2 * t] = u.x;
            xr[2 * t + 1] = u.y;
        }
        const float2* zr2 = reinterpret_cast<const float2*>(zp + p * 14);
        float zr[14];
#pragma unroll
        for (int t = 0; t < 7; t++) {
            float2 u = __ldg(zr2 + t);
            zr[2 * t] = u.x;
            zr[2 * t + 1] = u.y;
        }
#pragma unroll
        for (int q = 0; q < 14; q++) {
            float zv = zr[q];
#pragma unroll
            for (int j = 0; j < 17; j++)
                acc[j] = fmaf(zv, xr[q + j], acc[j]);
        }
    }

    float* op = out + bc * 289 + oh * 17;
#pragma unroll
    for (int j = 0; j < 17; j++) op[j] = acc[j];
}

// ===========================================================================
extern "C" void kernel_launch(void* const* d_in, const int* in_sizes, int n_in,
                              void* d_out, int out_size)
{
    const float* z       = (const float*)d_in[0];
    const float* x       = (const float*)d_in[1];
    const float* w_z     = (const float*)d_in[2];
    const float* w_x     = (const float*)d_in[3];
    const float* gamma_z = (const float*)d_in[4];
    const float* beta_z  = (const float*)d_in[5];
    const float* mean_z  = (const float*)d_in[6];
    const float* var_z   = (const float*)d_in[7];
    const float* gamma_x = (const float*)d_in[8];
    const float* beta_x  = (const float*)d_in[9];
    const float* mean_x  = (const float*)d_in[10];
    const float* var_x   = (const float*)d_in[11];
    float* out = (float*)d_out;

    float *zf, *xf;
    uint32_t *zp, *xp2;
    __half *wz16, *wx16;
    cudaGetSymbolAddress((void**)&zf, g_zf);
    cudaGetSymbolAddress((void**)&xf, g_xf);
    cudaGetSymbolAddress((void**)&zp, g_zp);
    cudaGetSymbolAddress((void**)&xp2, g_xp);
    cudaGetSymbolAddress((void**)&wz16, g_wz);
    cudaGetSymbolAddress((void**)&wx16, g_wx);

    constexpr int SMEM_BYTES = 73728;

    static bool attr_done = false;
    if (!attr_done) {
        cudaFuncSetAttribute(conv3x3_bn_wmma<14, 14, 16, 16>,
                             cudaFuncAttributeMaxDynamicSharedMemorySize, SMEM_BYTES);
        cudaFuncSetAttribute(conv3x3_bn_wmma<30, 30, 32, 32>,
                             cudaFuncAttributeMaxDynamicSharedMemorySize, SMEM_BYTES);
        attr_done = true;
    }

    // ---- pack inputs (fp16 hi/lo u32) + weights (fp16 plane) ----
    {
        int n4;
        n4 = 64 * 256 * 16 * 16 / 4;
        pack_in_kernel<<<(n4 + 255) / 256, 256>>>((const float4*)z, (uint4*)zp, n4);
        n4 = 64 * 256 * 32 * 32 / 4;
        pack_in_kernel<<<(n4 + 255) / 256, 256>>>((const float4*)x, (uint4*)xp2, n4);
        n4 = 256 * 2304 / 4;
        pack_w_kernel<<<(n4 + 255) / 256, 256>>>((const float4*)w_z, (uint2*)wz16, n4);
        pack_w_kernel<<<(n4 + 255) / 256, 256>>>((const float4*)w_x, (uint2*)wx16, n4);
    }

    // z branch: N = 12544 = 196 * 64
    conv3x3_bn_wmma<14, 14, 16, 16><<<dim3(196, 2), 256, SMEM_BYTES>>>(
        zp, wz16, gamma_z, beta_z, mean_z, var_z, zf);

    // x branch: N = 57600 = 900 * 64
    conv3x3_bn_wmma<30, 30, 32, 32><<<dim3(900, 2), 256, SMEM_BYTES>>>(
        xp2, wx16, gamma_x, beta_x, mean_x, var_x, xf);

    // xcorr
    xcorr_kernel<<<1088, 256>>>(zf, xf, out);
}

// round 8
// speedup vs baseline: 3.7370x; 1.0732x over previous
#include <cuda_runtime.h>
#include <cuda_fp16.h>
#include <mma.h>
#include <cstdint>

using namespace nvcuda;

#define EPS 1e-5f

// Scratch (no cudaMalloc allowed).
__device__ __align__(16) float    g_zf[64 * 256 * 14 * 14];     // 12.8 MB
__device__ __align__(16) float    g_xf[64 * 256 * 30 * 30];     // 59 MB
__device__ __align__(16) uint32_t g_zp[64 * 256 * 16 * 16];     // packed z (fp16 hi|lo)
__device__ __align__(16) uint32_t g_xp[64 * 256 * 32 * 32];     // packed x (fp16 hi|lo)
__device__ __align__(16) __half   g_wz[256 * 2304];             // fp16 weights z
__device__ __align__(16) __half   g_wx[256 * 2304];             // fp16 weights x

__device__ __forceinline__ uint32_t prmt(uint32_t a, uint32_t b, uint32_t sel) {
    uint32_t r;
    asm("prmt.b32 %0, %1, %2, %3;" : "=r"(r) : "r"(a), "r"(b), "r"(sel));
    return r;
}

__device__ __forceinline__ uint32_t smem_u32(const void* p) {
    uint32_t a;
    asm("{ .reg .u64 t; cvta.to.shared.u64 t, %1; cvt.u32.u64 %0, t; }"
        : "=r"(a) : "l"(p));
    return a;
}

#define CP_ASYNC16(dst, src) \
    asm volatile("cp.async.cg.shared.global [%0], [%1], 16;" \
        :: "r"(dst), "l"(src) : "memory")
#define CP_COMMIT() asm volatile("cp.async.commit_group;" ::: "memory")
#define CP_WAIT0()  asm volatile("cp.async.wait_group 0;" ::: "memory")

// fp16 2-split pack: u32 = half(v) | half(v - half(v)) << 16
__device__ __forceinline__ uint32_t pack_h2(float v) {
    __half h = __float2half_rn(v);
    __half l = __float2half_rn(v - __half2float(h));
    return (uint32_t)__half_as_ushort(h) |
           ((uint32_t)__half_as_ushort(l) << 16);
}

// ---- pack inputs: fp32 -> u32 (fp16 hi | fp16 lo<<16) ----
__global__ void pack_in_kernel(const float4* __restrict__ src,
                               uint4* __restrict__ dst, int n4)
{
    int i = blockIdx.x * blockDim.x + threadIdx.x;
    if (i >= n4) return;
    float4 v = __ldg(src + i);
    dst[i] = make_uint4(pack_h2(v.x), pack_h2(v.y), pack_h2(v.z), pack_h2(v.w));
}

// ---- pack weights: fp32 -> single fp16 plane ----
__global__ void pack_w_kernel(const float4* __restrict__ src,
                              uint2* __restrict__ dst, int n4)
{
    int i = blockIdx.x * blockDim.x + threadIdx.x;
    if (i >= n4) return;
    float4 v = __ldg(src + i);
    __half2 h01 = __floats2half2_rn(v.x, v.y);
    __half2 h23 = __floats2half2_rn(v.z, v.w);
    dst[i] = make_uint2(*reinterpret_cast<uint32_t*>(&h01),
                        *reinterpret_cast<uint32_t*>(&h23));
}

// ===========================================================================
// Implicit-GEMM 3x3 conv + fused BN, fp16 wmma 2-split.
//   w*x ~= wh*xh + wh*xl  (weights single fp16, inputs split hi/lo)
// BM=256 (all out-channels), BN=64, BK=64, 256 threads, 8 warps,
// warp tile 64m x 32n (acc 4x2), 2 CTAs/SM. 36 k-iterations.
// ===========================================================================
template <int OH, int OW, int IH, int IW>
__global__ __launch_bounds__(256, 2)
void conv3x3_bn_wmma(const uint32_t* __restrict__ xp,   // packed input (hi|lo)
                     const __half* __restrict__ whalf,  // fp16 weights [256,2304]
                     const float* __restrict__ gamma,
                     const float* __restrict__ beta,
                     const float* __restrict__ mean,
                     const float* __restrict__ var,
                     float* __restrict__ out)           // [B,256,OH,OW]
{
    constexpr int C = 256, K = C * 9;
    constexpr int BM = 256, BN = 64, BK = 64;
    constexpr int NCH = K / BK;                 // 36
    constexpr int OHW = OH * OW;
    constexpr int LDA = 72;                     // fp16 elems/row (144 B)
    constexpr int LDC = 68;
    constexpr uint32_t A_T = BM * LDA * 2;      // 36864 (single plane)
    constexpr uint32_t B_T = BN * LDA * 2;      // 9216
    constexpr uint32_t OF_BHI = 2 * A_T;        // 73728
    constexpr uint32_t OF_BLO = OF_BHI + 2 * B_T;   // 92160
    // total smem = 110592

    extern __shared__ char smem[];
    const uint32_t sbase = smem_u32(smem);

    const int tid = threadIdx.x;
    const int wid = tid >> 5;
    const int n0 = blockIdx.x * BN;
    const int wm = (wid >> 1) * 64;             // 4 m-warps
    const int wn = (wid & 1) * 32;              // 2 n-warps

    // --- A fill (cp.async): 8 chunks, chunk i: row r0+32i, 16B sub q ---
    const int r0 = tid >> 3;            // 0..31
    const int q  = tid & 7;             // 0..7  (16B = 8 fp16 along k)
    const __half* whp = whalf + (size_t)r0 * K + q * 8;
    const uint32_t ad0 = (uint32_t)(r0 * 144 + q * 16);

    // --- B fill: one n, 16 k's per thread ---
    const int n_loc = tid & 63;
    const int koff  = (tid >> 6) * 16;  // 0,16,32,48
    const int n     = n0 + n_loc;
    const int b_    = n / OHW;
    const int rem   = n - b_ * OHW;
    const int ohh   = rem / OW;
    const int oww   = rem - ohh * OW;
    const uint32_t* xb = xp + (size_t)b_ * C * IH * IW + (size_t)ohh * IW + oww;

    auto fillA = [&](int ch) {
        const uint32_t s = sbase + (uint32_t)(ch & 1) * A_T + ad0;
        const int ko = ch * BK;
#pragma unroll
        for (int i = 0; i < 8; i++)
            CP_ASYNC16(s + i * 4608u, whp + ko + (size_t)i * 32 * K);
    };

    auto ldgB = [&](int ch, uint32_t* v) {
        int kg = ch * BK + koff;
        int ci = kg / 9;
        int r9 = kg - ci * 9;
        int kh = r9 / 3;
        int kw = r9 - kh * 3;
#pragma unroll
        for (int j = 0; j < 16; j++) {
            v[j] = __ldg(xb + (ci * IH + kh) * IW + kw);
            kw++; if (kw == 3) { kw = 0; kh++; if (kh == 3) { kh = 0; ci++; } }
        }
    };
    auto stsB = [&](int ch, const uint32_t* v) {
        const int buf = ch & 1;
        uint32_t* dh = (uint32_t*)(smem + OF_BHI + buf * B_T) + n_loc * 36 + (koff >> 1);
        uint32_t* dl = (uint32_t*)(smem + OF_BLO + buf * B_T) + n_loc * 36 + (koff >> 1);
#pragma unroll
        for (int h = 0; h < 2; h++) {
            const uint32_t* s = v + h * 8;
            *reinterpret_cast<uint4*>(dh + h * 4) = make_uint4(
                prmt(s[0], s[1], 0x5410), prmt(s[2], s[3], 0x5410),
                prmt(s[4], s[5], 0x5410), prmt(s[6], s[7], 0x5410));
            *reinterpret_cast<uint4*>(dl + h * 4) = make_uint4(
                prmt(s[0], s[1], 0x7632), prmt(s[2], s[3], 0x7632),
                prmt(s[4], s[5], 0x7632), prmt(s[6], s[7], 0x7632));
        }
    };

    wmma::fragment<wmma::accumulator, 16, 16, 16, float> acc[4][2];
#pragma unroll
    for (int i = 0; i < 4; i++)
#pragma unroll
        for (int j = 0; j < 2; j++) wmma::fill_fragment(acc[i][j], 0.0f);

    // prologue: stage 0
    fillA(0);
    CP_COMMIT();
    {
        uint32_t v[16];
        ldgB(0, v);
        stsB(0, v);
    }

#pragma unroll 1
    for (int ch = 0; ch < NCH; ch++) {
        CP_WAIT0();
        __syncthreads();

        uint32_t v[16];
        const bool more = (ch + 1 < NCH);
        if (more) {
            fillA(ch + 1);
            CP_COMMIT();
            ldgB(ch + 1, v);           // LDGs in flight during MMA below
        }

        const int buf = ch & 1;
        const __half* sa   = (const __half*)(smem + buf * A_T);
        const __half* sb_h = (const __half*)(smem + OF_BHI + buf * B_T);
        const __half* sb_l = (const __half*)(smem + OF_BLO + buf * B_T);

#pragma unroll
        for (int ks = 0; ks < 4; ks++) {
            const int ko = ks * 16;
            wmma::fragment<wmma::matrix_b, 16, 16, 16, __half, wmma::col_major> bh[2], bl[2];
#pragma unroll
            for (int j = 0; j < 2; j++) {
                wmma::load_matrix_sync(bh[j], sb_h + (wn + j * 16) * LDA + ko, LDA);
                wmma::load_matrix_sync(bl[j], sb_l + (wn + j * 16) * LDA + ko, LDA);
            }
#pragma unroll
            for (int i = 0; i < 4; i++) {
                wmma::fragment<wmma::matrix_a, 16, 16, 16, __half, wmma::row_major> a;
                wmma::load_matrix_sync(a, sa + (wm + i * 16) * LDA + ko, LDA);
#pragma unroll
                for (int j = 0; j < 2; j++) {
                    wmma::mma_sync(acc[i][j], a, bh[j], acc[i][j]);
                    wmma::mma_sync(acc[i][j], a, bl[j], acc[i][j]);
                }
            }
        }

        if (more) stsB(ch + 1, v);     // after MMA: LDG latency covered
    }

    // ---- epilogue: acc -> SMEM C tile -> BN -> NCHW scatter ----
    __syncthreads();
    float* ct = (float*)smem;                   // 256 x 68 fp32 = 69632 B
#pragma unroll
    for (int i = 0; i < 4; i++)
#pragma unroll
        for (int j = 0; j < 2; j++)
            wmma::store_matrix_sync(ct + (wm + i * 16) * LDC + wn + j * 16,
                                    acc[i][j], LDC, wmma::mem_row_major);
    __syncthreads();

#pragma unroll 1
    for (int it = 0; it < 64; it++) {
        const int idx = tid + it * 256;
        const int m = idx >> 6;                 // 0..255 (= channel)
        const int nl = idx & 63;
        const float sc = __ldg(&gamma[m]) * rsqrtf(__ldg(&var[m]) + EPS);
        const float bi = __ldg(&beta[m]) - __ldg(&mean[m]) * sc;
        const int nn = n0 + nl;
        const int b2 = nn / OHW;
        const int s  = nn - b2 * OHW;
        out[((size_t)b2 * C + m) * OHW + s] = ct[m * LDC + nl] * sc + bi;
    }
}

// ===========================================================================
// Depthwise cross-correlation (float2-vectorized loads).
// ===========================================================================
__global__ __launch_bounds__(256)
void xcorr_kernel(const float* __restrict__ zf,   // [BC,14,14]
                  const float* __restrict__ xf,   // [BC,30,30]
                  float* __restrict__ out)        // [BC,17,17]
{
    int g = blockIdx.x * blockDim.x + threadIdx.x;
    if (g >= 64 * 256 * 17) return;
    int oh = g % 17;
    int bc = g / 17;

    const float* zp = zf + bc * 196;
    const float* xp = xf + bc * 900;

    float acc[17];
#pragma unroll
    for (int j = 0; j < 17; j++) acc[j] = 0.f;

#pragma unroll 1
    for (int p = 0; p < 14; p++) {
        const float2* row2 = reinterpret_cast<const float2*>(xp + (oh + p) * 30);
        float xr[30];
#pragma unroll
        for (int t = 0; t < 15; t++) {
            float2 u = __ldg(row2 + t);
            xr[2 * t] = u.x;
            xr[2 * t + 1] = u.y;
        }
        const float2* zr2 = reinterpret_cast<const float2*>(zp + p * 14);
        float zr[14];
#pragma unroll
        for (int t = 0; t < 7; t++) {
            float2 u = __ldg(zr2 + t);
            zr[2 * t] = u.x;
            zr[2 * t + 1] = u.y;
        }
#pragma unroll
        for (int q = 0; q < 14; q++) {
            float zv = zr[q];
#pragma unroll
            for (int j = 0; j < 17; j++)
                acc[j] = fmaf(zv, xr[q + j], acc[j]);
        }
    }

    float* op = out + bc * 289 + oh * 17;
#pragma unroll
    for (int j = 0; j < 17; j++) op[j] = acc[j];
}

// ===========================================================================
extern "C" void kernel_launch(void* const* d_in, const int* in_sizes, int n_in,
                              void* d_out, int out_size)
{
    const float* z       = (const float*)d_in[0];
    const float* x       = (const float*)d_in[1];
    const float* w_z     = (const float*)d_in[2];
    const float* w_x     = (const float*)d_in[3];
    const float* gamma_z = (const float*)d_in[4];
    const float* beta_z  = (const float*)d_in[5];
    const float* mean_z  = (const float*)d_in[6];
    const float* var_z   = (const float*)d_in[7];
    const float* gamma_x = (const float*)d_in[8];
    const float* beta_x  = (const float*)d_in[9];
    const float* mean_x  = (const float*)d_in[10];
    const float* var_x   = (const float*)d_in[11];
    float* out = (float*)d_out;

    float *zf, *xf;
    uint32_t *zp, *xp2;
    __half *wz16, *wx16;
    cudaGetSymbolAddress((void**)&zf, g_zf);
    cudaGetSymbolAddress((void**)&xf, g_xf);
    cudaGetSymbolAddress((void**)&zp, g_zp);
    cudaGetSymbolAddress((void**)&xp2, g_xp);
    cudaGetSymbolAddress((void**)&wz16, g_wz);
    cudaGetSymbolAddress((void**)&wx16, g_wx);

    constexpr int SMEM_BYTES = 110592;

    static bool attr_done = false;
    if (!attr_done) {
        cudaFuncSetAttribute(conv3x3_bn_wmma<14, 14, 16, 16>,
                             cudaFuncAttributeMaxDynamicSharedMemorySize, SMEM_BYTES);
        cudaFuncSetAttribute(conv3x3_bn_wmma<30, 30, 32, 32>,
                             cudaFuncAttributeMaxDynamicSharedMemorySize, SMEM_BYTES);
        attr_done = true;
    }

    // ---- pack inputs (fp16 hi/lo u32) + weights (fp16 plane) ----
    {
        int n4;
        n4 = 64 * 256 * 16 * 16 / 4;
        pack_in_kernel<<<(n4 + 255) / 256, 256>>>((const float4*)z, (uint4*)zp, n4);
        n4 = 64 * 256 * 32 * 32 / 4;
        pack_in_kernel<<<(n4 + 255) / 256, 256>>>((const float4*)x, (uint4*)xp2, n4);
        n4 = 256 * 2304 / 4;
        pack_w_kernel<<<(n4 + 255) / 256, 256>>>((const float4*)w_z, (uint2*)wz16, n4);
        pack_w_kernel<<<(n4 + 255) / 256, 256>>>((const float4*)w_x, (uint2*)wx16, n4);
    }

    // z branch: N = 12544 = 196 * 64, single m-tile
    conv3x3_bn_wmma<14, 14, 16, 16><<<dim3(196, 1), 256, SMEM_BYTES>>>(
        zp, wz16, gamma_z, beta_z, mean_z, var_z, zf);

    // x branch: N = 57600 = 900 * 64, single m-tile
    conv3x3_bn_wmma<30, 30, 32, 32><<<dim3(900, 1), 256, SMEM_BYTES>>>(
        xp2, wx16, gamma_x, beta_x, mean_x, var_x, xf);

    // xcorr
    xcorr_kernel<<<1088, 256>>>(zf, xf, out);
}

// round 9
// speedup vs baseline: 3.7581x; 1.0057x over previous
#include <cuda_runtime.h>
#include <cuda_fp16.h>
#include <mma.h>
#include <cstdint>

using namespace nvcuda;

#define EPS 1e-5f

// Scratch (no cudaMalloc allowed).
__device__ __align__(16) float    g_zf[64 * 256 * 14 * 14];     // 12.8 MB
__device__ __align__(16) float    g_xf[64 * 256 * 30 * 30];     // 59 MB
__device__ __align__(16) uint32_t g_zp[64 * 256 * 16 * 16];     // packed z (fp16 hi|lo)
__device__ __align__(16) uint32_t g_xp[64 * 256 * 32 * 32];     // packed x (fp16 hi|lo)
__device__ __align__(16) __half   g_wz[256 * 2304];             // fp16 weights z
__device__ __align__(16) __half   g_wx[256 * 2304];             // fp16 weights x

__device__ __forceinline__ uint32_t prmt(uint32_t a, uint32_t b, uint32_t sel) {
    uint32_t r;
    asm("prmt.b32 %0, %1, %2, %3;" : "=r"(r) : "r"(a), "r"(b), "r"(sel));
    return r;
}

__device__ __forceinline__ uint32_t smem_u32(const void* p) {
    uint32_t a;
    asm("{ .reg .u64 t; cvta.to.shared.u64 t, %1; cvt.u32.u64 %0, t; }"
        : "=r"(a) : "l"(p));
    return a;
}

#define CP_ASYNC16(dst, src) \
    asm volatile("cp.async.cg.shared.global [%0], [%1], 16;" \
        :: "r"(dst), "l"(src) : "memory")
#define CP_COMMIT() asm volatile("cp.async.commit_group;" ::: "memory")
#define CP_WAIT0()  asm volatile("cp.async.wait_group 0;" ::: "memory")

// ---- packed fp32x2 helpers (Blackwell family) ----
#define PACKF2(d, lo, hi) \
    asm("mov.b64 %0, {%1, %2};" : "=l"(d) : "f"(lo), "f"(hi))
#define UNPACKF2(lo, hi, s) \
    asm("mov.b64 {%0, %1}, %2;" : "=f"(lo), "=f"(hi) : "l"(s))
#define FMA_F32X2(d, a, b) \
    asm("fma.rn.f32x2 %0, %1, %2, %0;" : "+l"(d) : "l"(a), "l"(b))

// fp16 2-split pack: u32 = half(v) | half(v - half(v)) << 16
__device__ __forceinline__ uint32_t pack_h2(float v) {
    __half h = __float2half_rn(v);
    __half l = __float2half_rn(v - __half2float(h));
    return (uint32_t)__half_as_ushort(h) |
           ((uint32_t)__half_as_ushort(l) << 16);
}

// ---- pack inputs: fp32 -> u32 (fp16 hi | fp16 lo<<16) ----
__global__ void pack_in_kernel(const float4* __restrict__ src,
                               uint4* __restrict__ dst, int n4)
{
    int i = blockIdx.x * blockDim.x + threadIdx.x;
    if (i >= n4) return;
    float4 v = __ldg(src + i);
    dst[i] = make_uint4(pack_h2(v.x), pack_h2(v.y), pack_h2(v.z), pack_h2(v.w));
}

// ---- pack weights: fp32 -> single fp16 plane ----
__global__ void pack_w_kernel(const float4* __restrict__ src,
                              uint2* __restrict__ dst, int n4)
{
    int i = blockIdx.x * blockDim.x + threadIdx.x;
    if (i >= n4) return;
    float4 v = __ldg(src + i);
    __half2 h01 = __floats2half2_rn(v.x, v.y);
    __half2 h23 = __floats2half2_rn(v.z, v.w);
    dst[i] = make_uint2(*reinterpret_cast<uint32_t*>(&h01),
                        *reinterpret_cast<uint32_t*>(&h23));
}

// ===========================================================================
// Implicit-GEMM 3x3 conv + fused BN, fp16 wmma 2-split.
//   w*x ~= wh*xh + wh*xl  (weights single fp16, inputs split hi/lo)
// BM=256, BN=64, BK=64, 256 threads, warp tile 64x32, 2 CTAs/SM.
// ===========================================================================
template <int OH, int OW, int IH, int IW>
__global__ __launch_bounds__(256, 2)
void conv3x3_bn_wmma(const uint32_t* __restrict__ xp,   // packed input (hi|lo)
                     const __half* __restrict__ whalf,  // fp16 weights [256,2304]
                     const float* __restrict__ gamma,
                     const float* __restrict__ beta,
                     const float* __restrict__ mean,
                     const float* __restrict__ var,
                     float* __restrict__ out)           // [B,256,OH,OW]
{
    constexpr int C = 256, K = C * 9;
    constexpr int BM = 256, BN = 64, BK = 64;
    constexpr int NCH = K / BK;                 // 36
    constexpr int OHW = OH * OW;
    constexpr int LDA = 72;                     // fp16 elems/row (144 B)
    constexpr int LDC = 68;
    constexpr uint32_t A_T = BM * LDA * 2;      // 36864 (single plane)
    constexpr uint32_t B_T = BN * LDA * 2;      // 9216
    constexpr uint32_t OF_BHI = 2 * A_T;        // 73728
    constexpr uint32_t OF_BLO = OF_BHI + 2 * B_T;   // 92160
    // total smem = 110592

    extern __shared__ char smem[];
    const uint32_t sbase = smem_u32(smem);

    const int tid = threadIdx.x;
    const int wid = tid >> 5;
    const int n0 = blockIdx.x * BN;
    const int wm = (wid >> 1) * 64;             // 4 m-warps
    const int wn = (wid & 1) * 32;              // 2 n-warps

    // --- A fill (cp.async): 8 chunks, chunk i: row r0+32i, 16B sub q ---
    const int r0 = tid >> 3;            // 0..31
    const int q  = tid & 7;             // 0..7  (16B = 8 fp16 along k)
    const __half* whp = whalf + (size_t)r0 * K + q * 8;
    const uint32_t ad0 = (uint32_t)(r0 * 144 + q * 16);

    // --- B fill: one n, 16 k's per thread ---
    const int n_loc = tid & 63;
    const int koff  = (tid >> 6) * 16;  // 0,16,32,48
    const int n     = n0 + n_loc;
    const int b_    = n / OHW;
    const int rem   = n - b_ * OHW;
    const int ohh   = rem / OW;
    const int oww   = rem - ohh * OW;
    const uint32_t* xb = xp + (size_t)b_ * C * IH * IW + (size_t)ohh * IW + oww;

    auto fillA = [&](int ch) {
        const uint32_t s = sbase + (uint32_t)(ch & 1) * A_T + ad0;
        const int ko = ch * BK;
#pragma unroll
        for (int i = 0; i < 8; i++)
            CP_ASYNC16(s + i * 4608u, whp + ko + (size_t)i * 32 * K);
    };

    auto ldgB = [&](int ch, uint32_t* v) {
        int kg = ch * BK + koff;
        int ci = kg / 9;
        int r9 = kg - ci * 9;
        int kh = r9 / 3;
        int kw = r9 - kh * 3;
#pragma unroll
        for (int j = 0; j < 16; j++) {
            v[j] = __ldg(xb + (ci * IH + kh) * IW + kw);
            kw++; if (kw == 3) { kw = 0; kh++; if (kh == 3) { kh = 0; ci++; } }
        }
    };
    auto stsB = [&](int ch, const uint32_t* v) {
        const int buf = ch & 1;
        uint32_t* dh = (uint32_t*)(smem + OF_BHI + buf * B_T) + n_loc * 36 + (koff >> 1);
        uint32_t* dl = (uint32_t*)(smem + OF_BLO + buf * B_T) + n_loc * 36 + (koff >> 1);
#pragma unroll
        for (int h = 0; h < 2; h++) {
            const uint32_t* s = v + h * 8;
            *reinterpret_cast<uint4*>(dh + h * 4) = make_uint4(
                prmt(s[0], s[1], 0x5410), prmt(s[2], s[3], 0x5410),
                prmt(s[4], s[5], 0x5410), prmt(s[6], s[7], 0x5410));
            *reinterpret_cast<uint4*>(dl + h * 4) = make_uint4(
                prmt(s[0], s[1], 0x7632), prmt(s[2], s[3], 0x7632),
                prmt(s[4], s[5], 0x7632), prmt(s[6], s[7], 0x7632));
        }
    };

    wmma::fragment<wmma::accumulator, 16, 16, 16, float> acc[4][2];
#pragma unroll
    for (int i = 0; i < 4; i++)
#pragma unroll
        for (int j = 0; j < 2; j++) wmma::fill_fragment(acc[i][j], 0.0f);

    // prologue: stage 0
    fillA(0);
    CP_COMMIT();
    {
        uint32_t v[16];
        ldgB(0, v);
        stsB(0, v);
    }

#pragma unroll 1
    for (int ch = 0; ch < NCH; ch++) {
        CP_WAIT0();
        __syncthreads();

        uint32_t v[16];
        const bool more = (ch + 1 < NCH);
        if (more) {
            fillA(ch + 1);
            CP_COMMIT();
            ldgB(ch + 1, v);           // LDGs in flight during MMA below
        }

        const int buf = ch & 1;
        const __half* sa   = (const __half*)(smem + buf * A_T);
        const __half* sb_h = (const __half*)(smem + OF_BHI + buf * B_T);
        const __half* sb_l = (const __half*)(smem + OF_BLO + buf * B_T);

#pragma unroll
        for (int ks = 0; ks < 4; ks++) {
            const int ko = ks * 16;
            wmma::fragment<wmma::matrix_b, 16, 16, 16, __half, wmma::col_major> bh[2], bl[2];
#pragma unroll
            for (int j = 0; j < 2; j++) {
                wmma::load_matrix_sync(bh[j], sb_h + (wn + j * 16) * LDA + ko, LDA);
                wmma::load_matrix_sync(bl[j], sb_l + (wn + j * 16) * LDA + ko, LDA);
            }
#pragma unroll
            for (int i = 0; i < 4; i++) {
                wmma::fragment<wmma::matrix_a, 16, 16, 16, __half, wmma::row_major> a;
                wmma::load_matrix_sync(a, sa + (wm + i * 16) * LDA + ko, LDA);
#pragma unroll
                for (int j = 0; j < 2; j++) {
                    wmma::mma_sync(acc[i][j], a, bh[j], acc[i][j]);
                    wmma::mma_sync(acc[i][j], a, bl[j], acc[i][j]);
                }
            }
        }

        if (more) stsB(ch + 1, v);     // after MMA: LDG latency covered
    }

    // ---- epilogue: acc -> SMEM C tile -> BN -> NCHW scatter ----
    __syncthreads();
    float* ct = (float*)smem;                   // 256 x 68 fp32 = 69632 B
#pragma unroll
    for (int i = 0; i < 4; i++)
#pragma unroll
        for (int j = 0; j < 2; j++)
            wmma::store_matrix_sync(ct + (wm + i * 16) * LDC + wn + j * 16,
                                    acc[i][j], LDC, wmma::mem_row_major);
    __syncthreads();

#pragma unroll 1
    for (int it = 0; it < 64; it++) {
        const int idx = tid + it * 256;
        const int m = idx >> 6;                 // 0..255 (= channel)
        const int nl = idx & 63;
        const float sc = __ldg(&gamma[m]) * rsqrtf(__ldg(&var[m]) + EPS);
        const float bi = __ldg(&beta[m]) - __ldg(&mean[m]) * sc;
        const int nn = n0 + nl;
        const int b2 = nn / OHW;
        const int s  = nn - b2 * OHW;
        out[((size_t)b2 * C + m) * OHW + s] = ct[m * LDC + nl] * sc + bi;
    }
}

// ===========================================================================
// Depthwise cross-correlation, packed f32x2 FMA.
// Per output j, f32x2 lanes hold (even-q, odd-q) partial sums; horizontal
// add at the end. a-operand (zr pairs) comes free from float2 loads; b needs
// even-parity (free) and odd-parity (14 packs/row) xr pairs.
// ===========================================================================
__global__ __launch_bounds__(256)
void xcorr_kernel(const float* __restrict__ zf,   // [BC,14,14]
                  const float* __restrict__ xf,   // [BC,30,30]
                  float* __restrict__ out)        // [BC,17,17]
{
    int g = blockIdx.x * blockDim.x + threadIdx.x;
    if (g >= 64 * 256 * 17) return;
    int oh = g % 17;
    int bc = g / 17;

    const float* zp = zf + bc * 196;
    const float* xp = xf + bc * 900;

    unsigned long long acc2[17];
#pragma unroll
    for (int j = 0; j < 17; j++) acc2[j] = 0ull;

#pragma unroll 1
    for (int p = 0; p < 14; p++) {
        // xf row: 15 float2 loads -> even pairs xe, odd pairs xo
        const float2* row2 = reinterpret_cast<const float2*>(xp + (oh + p) * 30);
        float2 u[15];
#pragma unroll
        for (int t = 0; t < 15; t++) u[t] = __ldg(row2 + t);
        unsigned long long xe[15], xo[14];
#pragma unroll
        for (int t = 0; t < 15; t++) PACKF2(xe[t], u[t].x, u[t].y);
#pragma unroll
        for (int t = 0; t < 14; t++) PACKF2(xo[t], u[t].y, u[t + 1].x);

        // zf row: 7 float2 loads = 7 q-pairs (free f32x2 operands)
        const float2* zr2 = reinterpret_cast<const float2*>(zp + p * 14);
        unsigned long long z2[7];
#pragma unroll
        for (int t = 0; t < 7; t++) {
            float2 u2 = __ldg(zr2 + t);
            PACKF2(z2[t], u2.x, u2.y);
        }

#pragma unroll
        for (int qq = 0; qq < 7; qq++) {
#pragma unroll
            for (int j = 0; j < 17; j++) {
                // b = (xr[2qq+j], xr[2qq+j+1])
                if (j & 1) {
                    FMA_F32X2(acc2[j], z2[qq], xo[qq + ((j - 1) >> 1)]);
                } else {
                    FMA_F32X2(acc2[j], z2[qq], xe[qq + (j >> 1)]);
                }
            }
        }
    }

    float* op = out + bc * 289 + oh * 17;
#pragma unroll
    for (int j = 0; j < 17; j++) {
        float lo, hi;
        UNPACKF2(lo, hi, acc2[j]);
        op[j] = lo + hi;
    }
}

// ===========================================================================
extern "C" void kernel_launch(void* const* d_in, const int* in_sizes, int n_in,
                              void* d_out, int out_size)
{
    const float* z       = (const float*)d_in[0];
    const float* x       = (const float*)d_in[1];
    const float* w_z     = (const float*)d_in[2];
    const float* w_x     = (const float*)d_in[3];
    const float* gamma_z = (const float*)d_in[4];
    const float* beta_z  = (const float*)d_in[5];
    const float* mean_z  = (const float*)d_in[6];
    const float* var_z   = (const float*)d_in[7];
    const float* gamma_x = (const float*)d_in[8];
    const float* beta_x  = (const float*)d_in[9];
    const float* mean_x  = (const float*)d_in[10];
    const float* var_x   = (const float*)d_in[11];
    float* out = (float*)d_out;

    float *zf, *xf;
    uint32_t *zp, *xp2;
    __half *wz16, *wx16;
    cudaGetSymbolAddress((void**)&zf, g_zf);
    cudaGetSymbolAddress((void**)&xf, g_xf);
    cudaGetSymbolAddress((void**)&zp, g_zp);
    cudaGetSymbolAddress((void**)&xp2, g_xp);
    cudaGetSymbolAddress((void**)&wz16, g_wz);
    cudaGetSymbolAddress((void**)&wx16, g_wx);

    constexpr int SMEM_BYTES = 110592;

    static bool attr_done = false;
    if (!attr_done) {
        cudaFuncSetAttribute(conv3x3_bn_wmma<14, 14, 16, 16>,
                             cudaFuncAttributeMaxDynamicSharedMemorySize, SMEM_BYTES);
        cudaFuncSetAttribute(conv3x3_bn_wmma<30, 30, 32, 32>,
                             cudaFuncAttributeMaxDynamicSharedMemorySize, SMEM_BYTES);
        attr_done = true;
    }

    // ---- pack inputs (fp16 hi/lo u32) + weights (fp16 plane) ----
    {
        int n4;
        n4 = 64 * 256 * 16 * 16 / 4;
        pack_in_kernel<<<(n4 + 255) / 256, 256>>>((const float4*)z, (uint4*)zp, n4);
        n4 = 64 * 256 * 32 * 32 / 4;
        pack_in_kernel<<<(n4 + 255) / 256, 256>>>((const float4*)x, (uint4*)xp2, n4);
        n4 = 256 * 2304 / 4;
        pack_w_kernel<<<(n4 + 255) / 256, 256>>>((const float4*)w_z, (uint2*)wz16, n4);
        pack_w_kernel<<<(n4 + 255) / 256, 256>>>((const float4*)w_x, (uint2*)wx16, n4);
    }

    // z branch: N = 12544 = 196 * 64, single m-tile
    conv3x3_bn_wmma<14, 14, 16, 16><<<dim3(196, 1), 256, SMEM_BYTES>>>(
        zp, wz16, gamma_z, beta_z, mean_z, var_z, zf);

    // x branch: N = 57600 = 900 * 64, single m-tile
    conv3x3_bn_wmma<30, 30, 32, 32><<<dim3(900, 1), 256, SMEM_BYTES>>>(
        xp2, wx16, gamma_x, beta_x, mean_x, var_x, xf);

    // xcorr
    xcorr_kernel<<<1088, 256>>>(zf, xf, out);
}